// round 4
// baseline (speedup 1.0000x reference)
#include <cuda_runtime.h>
#include <math.h>
#include <stdint.h>

// ---------------- problem constants ----------------
#define B_    32
#define HH    28
#define WW    28
#define HID   1024
#define NH    16
#define DH    64
#define ROWS  25088
#define BNG   512
#define GSZ   50176

#define ALPHA_F 0.0828476643f
#define LN1E4_16 0.5756462732485114f
#define QDIV 32512.0f

// ---------------- scratch ----------------
__device__ float g_Yqk[(size_t)ROWS * 2048];
__device__ float g_xsum[B_ * WW * HID];
__device__ float g_isum[B_ * WW * HID];
__device__ float g_vsum[B_ * WW * HID];
__device__ float g_O[(size_t)BNG * GSZ];
__device__ float4 g_stats4[BNG];
__device__ float2 g_ac[BNG];
__device__ unsigned g_sbits[8];
// int8 hi/lo interleaved: row stride 2048, hi at [row*2048+k], lo at +1024
__device__ int8_t g_xq[(size_t)ROWS * 2048];
__device__ int8_t g_xsq[B_ * WW * 2048];
__device__ int8_t g_Zq[(size_t)ROWS * 2048];
__device__ int8_t g_Wq[(size_t)3072 * 2048];
__device__ int8_t g_Oq[(size_t)1024 * 2048];

// ---------------- helpers ----------------
__device__ __forceinline__ uint32_t smem_u32(const void* p) {
    uint32_t a;
    asm("{ .reg .u64 t; cvta.to.shared.u64 t, %1; cvt.u32.u64 %0, t; }" : "=r"(a) : "l"(p));
    return a;
}
#define SWZ64(x) ((x) ^ (((x) >> 3) & 0x30))

__device__ __forceinline__ void cp16(uint32_t saddr, const void* g) {
    asm volatile("cp.async.cg.shared.global [%0], [%1], 16;" :: "r"(saddr), "l"(g));
}
__device__ __forceinline__ void cp_commit() {
    asm volatile("cp.async.commit_group;" ::: "memory");
}
__device__ __forceinline__ void cp_wait0() {
    asm volatile("cp.async.wait_group 0;" ::: "memory");
}
__device__ __forceinline__ void ldm_x4(uint32_t& r0, uint32_t& r1, uint32_t& r2, uint32_t& r3,
                                       uint32_t addr) {
    asm volatile("ldmatrix.sync.aligned.m8n8.x4.shared.b16 {%0,%1,%2,%3}, [%4];"
                 : "=r"(r0), "=r"(r1), "=r"(r2), "=r"(r3) : "r"(addr));
}
__device__ __forceinline__ void mma_s8(int* d, const uint32_t* a, const uint32_t* b) {
    asm volatile(
        "mma.sync.aligned.m16n8k32.row.col.s32.s8.s8.s32 "
        "{%0,%1,%2,%3}, {%4,%5,%6,%7}, {%8,%9}, {%0,%1,%2,%3};"
        : "+r"(d[0]), "+r"(d[1]), "+r"(d[2]), "+r"(d[3])
        : "r"(a[0]), "r"(a[1]), "r"(a[2]), "r"(a[3]), "r"(b[0]), "r"(b[1]));
}

__device__ __forceinline__ float slot_max(int slot) {
    return fmaxf(__uint_as_float(g_sbits[slot]), 1e-30f);
}
// quantize q = v * (QDIV/max): hi = round(q/256) in [-127,127], lo = round(q)-256*hi clamped
__device__ __forceinline__ void quant2(float q, int& h, int& l) {
    h = __float2int_rn(q * 0.00390625f);
    l = __float2int_rn(q) - (h << 8);
    l = max(-127, min(127, l));
}

// ---------------- zero scale slots ----------------
__global__ void zero_kernel() {
    if (threadIdx.x < 8) g_sbits[threadIdx.x] = 0u;
}

// ---------------- absmax over n4 float4s ----------------
__global__ void absmax_kernel(const float* __restrict__ p, int n4, int slot) {
    float m = 0.f;
    for (int i = blockIdx.x * blockDim.x + threadIdx.x; i < n4; i += gridDim.x * blockDim.x) {
        float4 v = ((const float4*)p)[i];
        m = fmaxf(m, fmaxf(fmaxf(fabsf(v.x), fabsf(v.y)), fmaxf(fabsf(v.z), fabsf(v.w))));
    }
#pragma unroll
    for (int o = 16; o > 0; o >>= 1) m = fmaxf(m, __shfl_xor_sync(0xffffffffu, m, o));
    __shared__ float sh[8];
    if ((threadIdx.x & 31) == 0) sh[threadIdx.x >> 5] = m;
    __syncthreads();
    if (threadIdx.x == 0) {
        float mm = sh[0];
#pragma unroll
        for (int i = 1; i < 8; i++) mm = fmaxf(mm, sh[i]);
        atomicMax(&g_sbits[slot], __float_as_uint(mm));
    }
}

// ---------------- sum over H of x, img; also absmax(x)->slot0, absmax(xsum)->slot3 ----------------
__global__ void sumhw_kernel(const float* __restrict__ x, const float* __restrict__ img,
                             float* __restrict__ xs, float* __restrict__ is_)
{
    int idx = blockIdx.x * 256 + threadIdx.x;      // exact: 917504
    int r = idx >> 10;
    int b = r / WW, w = r % WW;
    size_t base = ((size_t)b * (HH * WW) + w) * HID + (idx & 1023);
    float s1 = 0.f, s2 = 0.f, mx = 0.f;
#pragma unroll 4
    for (int h = 0; h < HH; h++) {
        float xv = x[base];
        s1 += xv;
        s2 += img[base];
        mx = fmaxf(mx, fabsf(xv));
        base += (size_t)WW * HID;
    }
    xs[idx] = s1;
    is_[idx] = s2;
    float ms = fabsf(s1);
#pragma unroll
    for (int o = 16; o > 0; o >>= 1) {
        mx = fmaxf(mx, __shfl_xor_sync(0xffffffffu, mx, o));
        ms = fmaxf(ms, __shfl_xor_sync(0xffffffffu, ms, o));
    }
    __shared__ float sh[16];
    int wi = threadIdx.x >> 5;
    if ((threadIdx.x & 31) == 0) { sh[wi] = mx; sh[8 + wi] = ms; }
    __syncthreads();
    if (threadIdx.x == 0) {
        float a = sh[0], c = sh[8];
#pragma unroll
        for (int i = 1; i < 8; i++) { a = fmaxf(a, sh[i]); c = fmaxf(c, sh[8 + i]); }
        atomicMax(&g_sbits[0], __float_as_uint(a));
        atomicMax(&g_sbits[3], __float_as_uint(c));
    }
}

// ---------------- fp32 -> int8 hi/lo (rows of 1024, out stride 2048) ----------------
__global__ void quantsplit_kernel(const float* __restrict__ X, int8_t* __restrict__ Q, int slot) {
    int i4 = (blockIdx.x * 256 + threadIdx.x) * 4;
    float rcp = QDIV / slot_max(slot);
    float4 v = *(const float4*)(X + i4);
    int row = i4 >> 10, k = i4 & 1023;
    int h0, l0, h1, l1, h2, l2, h3, l3;
    quant2(v.x * rcp, h0, l0);
    quant2(v.y * rcp, h1, l1);
    quant2(v.z * rcp, h2, l2);
    quant2(v.w * rcp, h3, l3);
    size_t o = (size_t)row * 2048 + k;
    *(char4*)(Q + o)        = make_char4((char)h0, (char)h1, (char)h2, (char)h3);
    *(char4*)(Q + o + 1024) = make_char4((char)l0, (char)l1, (char)l2, (char)l3);
}

// ---------------- weight transpose + quant split ----------------
__global__ void transcvt_kernel(const float* __restrict__ W, int ldw, int perm,
                                int8_t* __restrict__ Q, int slot)
{
    __shared__ float t[32][33];
    const int nb = blockIdx.x * 32, kb = blockIdx.y * 32;
    const int tx = threadIdx.x & 31, ty = threadIdx.x >> 5;
    float rcp = QDIV / slot_max(slot);
    int n = nb + tx;
    int sc = perm ? (n < 1024 ? n : (n < 2048 ? n + 1024 : n - 1024)) : n;
#pragma unroll
    for (int i = 0; i < 4; i++)
        t[ty + 8 * i][tx] = W[(size_t)(kb + ty + 8 * i) * ldw + sc];
    __syncthreads();
#pragma unroll
    for (int i = 0; i < 4; i++) {
        int nn = nb + ty + 8 * i, kk = kb + tx;
        int h, l;
        quant2(t[tx][ty + 8 * i] * rcp, h, l);
        size_t o = (size_t)nn * 2048 + kk;
        Q[o] = (int8_t)h;
        Q[o + 1024] = (int8_t)l;
    }
}

// ---------------- int8 GEMM with 4 partial products ----------------
// C[M,N] = dequant(A @ B^T). A, B: [rows][2048] int8 hi/lo interleaved.
// mode 0: plain. 1: += ALPHA*Add. 2: qk-fused (+ALPHA*img, gamma for col>=1024), ldc=2048.
#define GOFF_AH 0
#define GOFF_AL 8192
#define GOFF_BH 16384
#define GOFF_BL 24576
#define GSTAGE  32768
#define GSMEM   65536

__global__ void __launch_bounds__(256, 1) gemm_s8(
    const int8_t* __restrict__ A, const int8_t* __restrict__ B,
    float* __restrict__ C, const float* __restrict__ Add,
    int ldc, int slotA, int slotB, int mode)
{
    extern __shared__ char smem[];
    const uint32_t sb = smem_u32(smem);
    const int tid = threadIdx.x, lane = tid & 31, wid = tid >> 5;
    const int warp_m = wid & 3, warp_n = wid >> 2;
    const int mBase = blockIdx.y * 128, nBase = blockIdx.x * 128;

    int acc1[2][8][4], accX[2][8][4], acc4[2][8][4];
#pragma unroll
    for (int m = 0; m < 2; m++)
#pragma unroll
        for (int n = 0; n < 8; n++)
#pragma unroll
            for (int j = 0; j < 4; j++) { acc1[m][n][j] = 0; accX[m][n][j] = 0; acc4[m][n][j] = 0; }

    const int lrow = tid >> 2, lj = tid & 3;

    auto load_stage = [&](int c, int s) {
        uint32_t st = sb + s * GSTAGE;
        int kb = c * 64 + lj * 16;
#pragma unroll
        for (int i = 0; i < 2; i++) {
            int r = lrow + i * 64;
            uint32_t so = SWZ64(r * 64 + lj * 16);
            const int8_t* ap = A + (size_t)(mBase + r) * 2048 + kb;
            const int8_t* bp = B + (size_t)(nBase + r) * 2048 + kb;
            cp16(st + GOFF_AH + so, ap);
            cp16(st + GOFF_AL + so, ap + 1024);
            cp16(st + GOFF_BH + so, bp);
            cp16(st + GOFF_BL + so, bp + 1024);
        }
        cp_commit();
    };

    load_stage(0, 0);

    for (int c = 0; c < 16; c++) {
        cp_wait0();
        __syncthreads();
        if (c < 15) load_stage(c + 1, (c + 1) & 1);
        const uint32_t st = sb + (c & 1) * GSTAGE;
#pragma unroll
        for (int ks = 0; ks < 2; ks++) {
            const int kb = ks * 32 + (lane >> 4) * 16;
            uint32_t ah[2][4], al[2][4];
#pragma unroll
            for (int mt = 0; mt < 2; mt++) {
                int row = warp_m * 32 + mt * 16 + (lane & 15);
                ldm_x4(ah[mt][0], ah[mt][1], ah[mt][2], ah[mt][3],
                       st + GOFF_AH + SWZ64(row * 64 + kb));
                ldm_x4(al[mt][0], al[mt][1], al[mt][2], al[mt][3],
                       st + GOFF_AL + SWZ64(row * 64 + kb));
            }
#pragma unroll
            for (int np = 0; np < 4; np++) {
                int rown = warp_n * 64 + np * 16 + (lane & 15);
                uint32_t h0, h1, h2, h3, l0, l1, l2, l3;
                ldm_x4(h0, h1, h2, h3, st + GOFF_BH + SWZ64(rown * 64 + kb));
                ldm_x4(l0, l1, l2, l3, st + GOFF_BL + SWZ64(rown * 64 + kb));
                uint32_t bh0[2] = {h0, h2}, bh1[2] = {h1, h3};
                uint32_t bl0[2] = {l0, l2}, bl1[2] = {l1, l3};
#pragma unroll
                for (int mt = 0; mt < 2; mt++) {
                    mma_s8(acc1[mt][2 * np],     ah[mt], bh0);
                    mma_s8(accX[mt][2 * np],     ah[mt], bl0);
                    mma_s8(accX[mt][2 * np],     al[mt], bh0);
                    mma_s8(acc4[mt][2 * np],     al[mt], bl0);
                    mma_s8(acc1[mt][2 * np + 1], ah[mt], bh1);
                    mma_s8(accX[mt][2 * np + 1], ah[mt], bl1);
                    mma_s8(accX[mt][2 * np + 1], al[mt], bh1);
                    mma_s8(acc4[mt][2 * np + 1], al[mt], bl1);
                }
            }
        }
        __syncthreads();
    }

    const float s = (slot_max(slotA) * (1.f / QDIV)) * (slot_max(slotB) * (1.f / QDIV));
#pragma unroll
    for (int mt = 0; mt < 2; mt++) {
#pragma unroll
        for (int nt = 0; nt < 8; nt++) {
            int r0 = mBase + warp_m * 32 + mt * 16 + (lane >> 2);
            int cc = nBase + warp_n * 64 + nt * 8 + 2 * (lane & 3);
            float v[4];
#pragma unroll
            for (int j = 0; j < 4; j++)
                v[j] = (65536.f * (float)acc1[mt][nt][j] + 256.f * (float)accX[mt][nt][j]
                        + (float)acc4[mt][nt][j]) * s;
#pragma unroll
            for (int half = 0; half < 2; half++) {
                int r = r0 + half * 8;
#pragma unroll
                for (int q = 0; q < 2; q++) {
                    int col = cc + q;
                    float val = v[half * 2 + q];
                    size_t o = (size_t)r * ldc + col;
                    if (mode == 1) {
                        val += ALPHA_F * Add[o];
                    } else if (mode == 2) {
                        int ic = col & 1023;
                        val += ALPHA_F * Add[(size_t)r * 1024 + ic];
                        if (col >= 1024)
                            val *= (1.f - exp2f(-(float)(5 + (ic >> 6))));
                    }
                    C[o] = val;
                }
            }
        }
    }
}

// ---------------- attention per (b,n,h) ----------------
__global__ void __launch_bounds__(256) attn_kernel(
    const float* __restrict__ Yqk, const float* __restrict__ vsum,
    float* __restrict__ O)
{
    __shared__ float rq[1792], rk[1792], qs[1792], ks[1792], vs[1792], sc[784];

    const int id = blockIdx.x;
    const int h  = id % HH;
    const int bn = id / HH;
    const int n  = bn & (NH - 1);
    const int b  = bn >> 4;
    const int tid = threadIdx.x;

    for (int i = tid; i < 1792; i += 256) {
        int xr = i >> 6, d = i & 63;
        size_t rowbase = ((size_t)b * (HH * WW) + h * WW + xr);
        size_t gq = rowbase * 2048 + n * DH + d;
        rq[i] = Yqk[gq];
        rk[i] = Yqk[gq + 1024];
        vs[i] = vsum[(((size_t)b * WW + xr) * HID) + n * DH + d];
    }
    __syncthreads();

    for (int i = tid; i < 1792; i += 256) {
        int xr = i >> 6, d = i & 63;
        int j = d & 15;
        float ang = (d < 32 ? (float)h : (float)xr) * expf(-(float)j * LN1E4_16);
        float s, c;
        sincosf(ang, &s, &c);
        bool second = (d & 16) != 0;
        int partner = second ? i - 16 : i + 16;
        float sgn = second ? 1.f : -1.f;
        qs[i] = rq[i] * c + sgn * rq[partner] * s;
        ks[i] = rk[i] * c + sgn * rk[partner] * s;
    }
    __syncthreads();

    for (int i = tid; i < 784; i += 256) {
        int xr = i / WW, z = i % WW;
        const float* qp = &qs[xr * DH];
        const float* kp = &ks[z * DH];
        float accv = 0.f;
#pragma unroll 16
        for (int d = 0; d < DH; d++) accv += qp[d] * kp[d];
        sc[i] = accv;
    }
    __syncthreads();

    for (int i = tid; i < 1792; i += 256) {
        int w = i >> 6, d = i & 63;
        float accv = 0.f;
#pragma unroll
        for (int y = 0; y < WW; y++) accv += sc[w * WW + y] * vs[y * DH + d];
        O[(size_t)bn * GSZ + h * (WW * DH) + i] = accv;
    }
}

// ---------------- groupnorm stats (sum, sumsq, min, max) ----------------
__global__ void __launch_bounds__(256) stats_kernel(const float* __restrict__ O)
{
    int bn = blockIdx.x;
    const float* p = O + (size_t)bn * GSZ;
    float s = 0.f, ss = 0.f, mn = 3.4e38f, mx = -3.4e38f;
    for (int i = threadIdx.x; i < GSZ; i += 256) {
        float v = p[i];
        s += v; ss += v * v;
        mn = fminf(mn, v); mx = fmaxf(mx, v);
    }
#pragma unroll
    for (int o = 16; o > 0; o >>= 1) {
        s  += __shfl_down_sync(0xffffffffu, s,  o);
        ss += __shfl_down_sync(0xffffffffu, ss, o);
        mn = fminf(mn, __shfl_down_sync(0xffffffffu, mn, o));
        mx = fmaxf(mx, __shfl_down_sync(0xffffffffu, mx, o));
    }
    __shared__ float sh[32];
    int w = threadIdx.x >> 5, l = threadIdx.x & 31;
    if (l == 0) { sh[w] = s; sh[8 + w] = ss; sh[16 + w] = mn; sh[24 + w] = mx; }
    __syncthreads();
    if (threadIdx.x == 0) {
        float a = 0.f, b2 = 0.f, m1 = sh[16], m2 = sh[24];
#pragma unroll
        for (int i = 0; i < 8; i++) {
            a += sh[i]; b2 += sh[8 + i];
            m1 = fminf(m1, sh[16 + i]); m2 = fmaxf(m2, sh[24 + i]);
        }
        g_stats4[bn] = make_float4(a, b2, m1, m2);
    }
}

// ---------------- combine: per-group affine + global Z scale ----------------
__global__ void combine_kernel(const float* __restrict__ gnw, const float* __restrict__ gnb)
{
    int bn = threadIdx.x;   // 512 threads
    float4 st = g_stats4[bn];
    float inv = 1.f / (float)GSZ;
    float mu = st.x * inv;
    float var = st.y * inv - mu * mu;
    float rstd = rsqrtf(var + 1e-5f);
    int n = bn & (NH - 1);
    float a = rstd * gnw[n];
    float c = gnb[n] - mu * a;
    g_ac[bn] = make_float2(a, c);
    float zm = fmaxf(fabsf(a * st.w + c), fabsf(a * st.z + c));
#pragma unroll
    for (int o = 16; o > 0; o >>= 1) zm = fmaxf(zm, __shfl_xor_sync(0xffffffffu, zm, o));
    __shared__ float sh[16];
    if ((threadIdx.x & 31) == 0) sh[threadIdx.x >> 5] = zm;
    __syncthreads();
    if (threadIdx.x == 0) {
        float m = sh[0];
#pragma unroll
        for (int i = 1; i < 16; i++) m = fmaxf(m, sh[i]);
        g_sbits[4] = __float_as_uint(m);
    }
}

// ---------------- normalize + transpose + quant-split Z ----------------
__global__ void norm_kernel(const float* __restrict__ O, int8_t* __restrict__ Zq)
{
    size_t i4 = ((size_t)blockIdx.x * 256 + threadIdx.x) * 4;
    int bn = (int)(i4 / GSZ);
    int rem = (int)(i4 % GSZ);
    int n = bn & (NH - 1), b = bn >> 4;
    int h = rem / (WW * DH);
    int rem2 = rem % (WW * DH);
    int w = rem2 >> 6, d = rem2 & 63;
    float2 ac = g_ac[bn];
    float rcp = QDIV / slot_max(4);
    float4 o = *(const float4*)(O + i4);
    int h0, l0, h1, l1, h2, l2, h3, l3;
    quant2((ac.x * o.x + ac.y) * rcp, h0, l0);
    quant2((ac.x * o.y + ac.y) * rcp, h1, l1);
    quant2((ac.x * o.z + ac.y) * rcp, h2, l2);
    quant2((ac.x * o.w + ac.y) * rcp, h3, l3);
    size_t zo = ((size_t)b * (HH * WW) + h * WW + w) * 2048 + n * DH + d;
    *(char4*)(Zq + zo)        = make_char4((char)h0, (char)h1, (char)h2, (char)h3);
    *(char4*)(Zq + zo + 1024) = make_char4((char)l0, (char)l1, (char)l2, (char)l3);
}

// ---------------- launch ----------------
extern "C" void kernel_launch(void* const* d_in, const int* in_sizes, int n_in,
                              void* d_out, int out_size)
{
    const float* x    = (const float*)d_in[0];
    const float* img  = (const float*)d_in[1];
    const float* qkvw = (const float*)d_in[2];
    const float* ow   = (const float*)d_in[3];
    const float* gnw  = (const float*)d_in[4];
    const float* gnb  = (const float*)d_in[5];
    float* out = (float*)d_out;

    float *Yqk, *xs, *is_, *vs, *O;
    int8_t *xq, *xsq, *Zq, *Wq, *Oq;
    cudaGetSymbolAddress((void**)&Yqk, g_Yqk);
    cudaGetSymbolAddress((void**)&xs,  g_xsum);
    cudaGetSymbolAddress((void**)&is_, g_isum);
    cudaGetSymbolAddress((void**)&vs,  g_vsum);
    cudaGetSymbolAddress((void**)&O,   g_O);
    cudaGetSymbolAddress((void**)&xq,  g_xq);
    cudaGetSymbolAddress((void**)&xsq, g_xsq);
    cudaGetSymbolAddress((void**)&Zq,  g_Zq);
    cudaGetSymbolAddress((void**)&Wq,  g_Wq);
    cudaGetSymbolAddress((void**)&Oq,  g_Oq);

    cudaFuncSetAttribute(gemm_s8, cudaFuncAttributeMaxDynamicSharedMemorySize, GSMEM);

    // 1-5: scales, sums, quantized operands
    zero_kernel<<<1, 32>>>();
    absmax_kernel<<<384, 256>>>(qkvw, 3072 * 1024 / 4, 1);
    sumhw_kernel<<<3584, 256>>>(x, img, xs, is_);            // also slot0 (x), slot3 (xsum)
    transcvt_kernel<<<dim3(96, 32), 256>>>(qkvw, 3072, 1, Wq, 1);
    quantsplit_kernel<<<ROWS, 256>>>(x, xq, 0);              // 25088 blocks * 1024 elems

    // 6: Yqk = x @ [Wq|Wk] with fused alpha*img add + gamma  (M=25088, N=2048)
    gemm_s8<<<dim3(16, 196), 256, GSMEM>>>(xq, Wq, Yqk, img, 2048, 0, 1, 2);

    // 7-9: o_w quant, xsum quant
    absmax_kernel<<<256, 256>>>(ow, 1024 * 1024 / 4, 2);
    transcvt_kernel<<<dim3(32, 32), 256>>>(ow, 1024, 0, Oq, 2);
    quantsplit_kernel<<<B_ * WW, 256>>>(xs, xsq, 3);

    // 10: vsum = xsum @ Wv + ALPHA*isum  (M=896, N=1024; Wv rows [2048,3072))
    gemm_s8<<<dim3(8, 7), 256, GSMEM>>>(xsq, Wq + (size_t)2048 * 2048, vs, is_, 1024, 3, 1, 1);

    // 11: attention
    attn_kernel<<<BNG * HH, 256>>>(Yqk, vs, O);

    // 12-14: groupnorm + quantized Z
    stats_kernel<<<BNG, 256>>>(O);
    combine_kernel<<<1, 512>>>(gnw, gnb);
    norm_kernel<<<(int)(((size_t)BNG * GSZ) / 1024), 256>>>(O, Zq);

    // 15: out = Z @ o_w  (M=25088, N=1024)
    gemm_s8<<<dim3(8, 196), 256, GSMEM>>>(Zq, Oq, out, nullptr, 1024, 4, 2, 0);
}

// round 6
// speedup vs baseline: 1.2441x; 1.2441x over previous
#include <cuda_runtime.h>
#include <math.h>
#include <stdint.h>

// ---------------- problem constants ----------------
#define B_    32
#define HH    28
#define WW    28
#define HID   1024
#define NH    16
#define DH    64
#define ROWS  25088
#define BNG   512
#define GSZ   50176

#define ALPHA_F 0.0828476643f
#define LN1E4_16 0.5756462732485114f
#define QDIV 32512.0f

// ---------------- scratch ----------------
__device__ float g_Yqk[(size_t)ROWS * 2048];
__device__ float g_xsum[B_ * WW * HID];
__device__ float g_isum[B_ * WW * HID];
__device__ float g_vsum[B_ * WW * HID];
__device__ float g_O[(size_t)BNG * GSZ];
__device__ float4 g_stats4[BNG];
__device__ float2 g_ac[BNG];
__device__ unsigned g_sbits[8];
// int8 hi/lo interleaved: row stride 2048, hi at [row*2048+k], lo at +1024
__device__ int8_t g_xq[(size_t)ROWS * 2048];
__device__ int8_t g_xsq[B_ * WW * 2048];
__device__ int8_t g_Zq[(size_t)ROWS * 2048];
__device__ int8_t g_Wq[(size_t)3072 * 2048];
__device__ int8_t g_Oq[(size_t)1024 * 2048];

// ---------------- helpers ----------------
__device__ __forceinline__ uint32_t smem_u32(const void* p) {
    uint32_t a;
    asm("{ .reg .u64 t; cvta.to.shared.u64 t, %1; cvt.u32.u64 %0, t; }" : "=r"(a) : "l"(p));
    return a;
}
#define SWZ64(x) ((x) ^ (((x) >> 3) & 0x30))

__device__ __forceinline__ void cp16(uint32_t saddr, const void* g) {
    asm volatile("cp.async.cg.shared.global [%0], [%1], 16;" :: "r"(saddr), "l"(g));
}
__device__ __forceinline__ void cp_commit() {
    asm volatile("cp.async.commit_group;" ::: "memory");
}
__device__ __forceinline__ void cp_wait0() {
    asm volatile("cp.async.wait_group 0;" ::: "memory");
}
__device__ __forceinline__ void ldm_x4(uint32_t& r0, uint32_t& r1, uint32_t& r2, uint32_t& r3,
                                       uint32_t addr) {
    asm volatile("ldmatrix.sync.aligned.m8n8.x4.shared.b16 {%0,%1,%2,%3}, [%4];"
                 : "=r"(r0), "=r"(r1), "=r"(r2), "=r"(r3) : "r"(addr));
}
__device__ __forceinline__ void mma_s8(int* d, const uint32_t* a, const uint32_t* b) {
    asm volatile(
        "mma.sync.aligned.m16n8k32.row.col.s32.s8.s8.s32 "
        "{%0,%1,%2,%3}, {%4,%5,%6,%7}, {%8,%9}, {%0,%1,%2,%3};"
        : "+r"(d[0]), "+r"(d[1]), "+r"(d[2]), "+r"(d[3])
        : "r"(a[0]), "r"(a[1]), "r"(a[2]), "r"(a[3]), "r"(b[0]), "r"(b[1]));
}

__device__ __forceinline__ float slot_max(int slot) {
    return fmaxf(__uint_as_float(g_sbits[slot]), 1e-30f);
}
// quantize q = v * (QDIV/max): hi = round(q/256) in [-127,127], lo = round(q)-256*hi clamped
__device__ __forceinline__ void quant2(float q, int& h, int& l) {
    h = __float2int_rn(q * 0.00390625f);
    l = __float2int_rn(q) - (h << 8);
    l = max(-127, min(127, l));
}

// ---------------- zero scale slots ----------------
__global__ void zero_kernel() {
    if (threadIdx.x < 8) g_sbits[threadIdx.x] = 0u;
}

// ---------------- absmax over n4 float4s ----------------
__global__ void absmax_kernel(const float* __restrict__ p, int n4, int slot) {
    float m = 0.f;
    for (int i = blockIdx.x * blockDim.x + threadIdx.x; i < n4; i += gridDim.x * blockDim.x) {
        float4 v = ((const float4*)p)[i];
        m = fmaxf(m, fmaxf(fmaxf(fabsf(v.x), fabsf(v.y)), fmaxf(fabsf(v.z), fabsf(v.w))));
    }
#pragma unroll
    for (int o = 16; o > 0; o >>= 1) m = fmaxf(m, __shfl_xor_sync(0xffffffffu, m, o));
    __shared__ float sh[8];
    if ((threadIdx.x & 31) == 0) sh[threadIdx.x >> 5] = m;
    __syncthreads();
    if (threadIdx.x == 0) {
        float mm = sh[0];
#pragma unroll
        for (int i = 1; i < 8; i++) mm = fmaxf(mm, sh[i]);
        atomicMax(&g_sbits[slot], __float_as_uint(mm));
    }
}

// ---------------- sum over H of x, img; also absmax(x)->slot0, absmax(xsum)->slot3 ----------------
__global__ void sumhw_kernel(const float* __restrict__ x, const float* __restrict__ img,
                             float* __restrict__ xs, float* __restrict__ is_)
{
    int idx = blockIdx.x * 256 + threadIdx.x;      // exact: 917504
    int r = idx >> 10;
    int b = r / WW, w = r % WW;
    size_t base = ((size_t)b * (HH * WW) + w) * HID + (idx & 1023);
    float s1 = 0.f, s2 = 0.f, mx = 0.f;
#pragma unroll 4
    for (int h = 0; h < HH; h++) {
        float xv = x[base];
        s1 += xv;
        s2 += img[base];
        mx = fmaxf(mx, fabsf(xv));
        base += (size_t)WW * HID;
    }
    xs[idx] = s1;
    is_[idx] = s2;
    float ms = fabsf(s1);
#pragma unroll
    for (int o = 16; o > 0; o >>= 1) {
        mx = fmaxf(mx, __shfl_xor_sync(0xffffffffu, mx, o));
        ms = fmaxf(ms, __shfl_xor_sync(0xffffffffu, ms, o));
    }
    __shared__ float sh[16];
    int wi = threadIdx.x >> 5;
    if ((threadIdx.x & 31) == 0) { sh[wi] = mx; sh[8 + wi] = ms; }
    __syncthreads();
    if (threadIdx.x == 0) {
        float a = sh[0], c = sh[8];
#pragma unroll
        for (int i = 1; i < 8; i++) { a = fmaxf(a, sh[i]); c = fmaxf(c, sh[8 + i]); }
        atomicMax(&g_sbits[0], __float_as_uint(a));
        atomicMax(&g_sbits[3], __float_as_uint(c));
    }
}

// ---------------- fp32 -> int8 hi/lo (rows of 1024, out stride 2048) ----------------
__global__ void quantsplit_kernel(const float* __restrict__ X, int8_t* __restrict__ Q, int slot) {
    int i4 = (blockIdx.x * 256 + threadIdx.x) * 4;
    float rcp = QDIV / slot_max(slot);
    float4 v = *(const float4*)(X + i4);
    int row = i4 >> 10, k = i4 & 1023;
    int h0, l0, h1, l1, h2, l2, h3, l3;
    quant2(v.x * rcp, h0, l0);
    quant2(v.y * rcp, h1, l1);
    quant2(v.z * rcp, h2, l2);
    quant2(v.w * rcp, h3, l3);
    size_t o = (size_t)row * 2048 + k;
    *(char4*)(Q + o)        = make_char4((char)h0, (char)h1, (char)h2, (char)h3);
    *(char4*)(Q + o + 1024) = make_char4((char)l0, (char)l1, (char)l2, (char)l3);
}

// ---------------- weight transpose + quant split ----------------
__global__ void transcvt_kernel(const float* __restrict__ W, int ldw, int perm,
                                int8_t* __restrict__ Q, int slot)
{
    __shared__ float t[32][33];
    const int nb = blockIdx.x * 32, kb = blockIdx.y * 32;
    const int tx = threadIdx.x & 31, ty = threadIdx.x >> 5;
    float rcp = QDIV / slot_max(slot);
    int n = nb + tx;
    int sc = perm ? (n < 1024 ? n : (n < 2048 ? n + 1024 : n - 1024)) : n;
#pragma unroll
    for (int i = 0; i < 4; i++)
        t[ty + 8 * i][tx] = W[(size_t)(kb + ty + 8 * i) * ldw + sc];
    __syncthreads();
#pragma unroll
    for (int i = 0; i < 4; i++) {
        int nn = nb + ty + 8 * i, kk = kb + tx;
        int h, l;
        quant2(t[tx][ty + 8 * i] * rcp, h, l);
        size_t o = (size_t)nn * 2048 + kk;
        Q[o] = (int8_t)h;
        Q[o + 1024] = (int8_t)l;
    }
}

// ---------------- int8 GEMM, 3 partial products (hi*hi, hi*lo, lo*hi) ----------------
// C[M,N] = dequant(A @ B^T). A, B: [rows][2048] int8 hi/lo interleaved.
// mode 0: plain. 1: += ALPHA*Add. 2: qk-fused (+ALPHA*img, gamma for col>=1024), ldc=2048.
#define GOFF_AH 0
#define GOFF_AL 8192
#define GOFF_BH 16384
#define GOFF_BL 24576
#define GSTAGE  32768
#define GSMEM   65536

__global__ void __launch_bounds__(256, 1) gemm_s8(
    const int8_t* __restrict__ A, const int8_t* __restrict__ B,
    float* __restrict__ C, const float* __restrict__ Add,
    int ldc, int slotA, int slotB, int mode)
{
    extern __shared__ char smem[];
    const uint32_t sb = smem_u32(smem);
    const int tid = threadIdx.x, lane = tid & 31, wid = tid >> 5;
    const int warp_m = wid & 3, warp_n = wid >> 2;
    const int mBase = blockIdx.y * 128, nBase = blockIdx.x * 128;

    int acc1[2][8][4], accX[2][8][4];
#pragma unroll
    for (int m = 0; m < 2; m++)
#pragma unroll
        for (int n = 0; n < 8; n++)
#pragma unroll
            for (int j = 0; j < 4; j++) { acc1[m][n][j] = 0; accX[m][n][j] = 0; }

    const int lrow = tid >> 2, lj = tid & 3;

    auto load_stage = [&](int c, int s) {
        uint32_t st = sb + s * GSTAGE;
        int kb = c * 64 + lj * 16;
#pragma unroll
        for (int i = 0; i < 2; i++) {
            int r = lrow + i * 64;
            uint32_t so = SWZ64(r * 64 + lj * 16);
            const int8_t* ap = A + (size_t)(mBase + r) * 2048 + kb;
            const int8_t* bp = B + (size_t)(nBase + r) * 2048 + kb;
            cp16(st + GOFF_AH + so, ap);
            cp16(st + GOFF_AL + so, ap + 1024);
            cp16(st + GOFF_BH + so, bp);
            cp16(st + GOFF_BL + so, bp + 1024);
        }
        cp_commit();
    };

    load_stage(0, 0);

    for (int c = 0; c < 16; c++) {
        cp_wait0();
        __syncthreads();
        if (c < 15) load_stage(c + 1, (c + 1) & 1);
        const uint32_t st = sb + (c & 1) * GSTAGE;
#pragma unroll
        for (int ks = 0; ks < 2; ks++) {
            const int kb = ks * 32 + (lane >> 4) * 16;
            uint32_t ah[2][4], al[2][4];
#pragma unroll
            for (int mt = 0; mt < 2; mt++) {
                int row = warp_m * 32 + mt * 16 + (lane & 15);
                ldm_x4(ah[mt][0], ah[mt][1], ah[mt][2], ah[mt][3],
                       st + GOFF_AH + SWZ64(row * 64 + kb));
                ldm_x4(al[mt][0], al[mt][1], al[mt][2], al[mt][3],
                       st + GOFF_AL + SWZ64(row * 64 + kb));
            }
#pragma unroll
            for (int np = 0; np < 4; np++) {
                int rown = warp_n * 64 + np * 16 + (lane & 15);
                uint32_t h0, h1, h2, h3, l0, l1, l2, l3;
                ldm_x4(h0, h1, h2, h3, st + GOFF_BH + SWZ64(rown * 64 + kb));
                ldm_x4(l0, l1, l2, l3, st + GOFF_BL + SWZ64(rown * 64 + kb));
                uint32_t bh0[2] = {h0, h2}, bh1[2] = {h1, h3};
                uint32_t bl0[2] = {l0, l2}, bl1[2] = {l1, l3};
#pragma unroll
                for (int mt = 0; mt < 2; mt++) {
                    mma_s8(acc1[mt][2 * np],     ah[mt], bh0);
                    mma_s8(accX[mt][2 * np],     ah[mt], bl0);
                    mma_s8(accX[mt][2 * np],     al[mt], bh0);
                    mma_s8(acc1[mt][2 * np + 1], ah[mt], bh1);
                    mma_s8(accX[mt][2 * np + 1], ah[mt], bl1);
                    mma_s8(accX[mt][2 * np + 1], al[mt], bh1);
                }
            }
        }
        __syncthreads();
    }

    const float s = (slot_max(slotA) * (1.f / QDIV)) * (slot_max(slotB) * (1.f / QDIV));
#pragma unroll
    for (int mt = 0; mt < 2; mt++) {
#pragma unroll
        for (int nt = 0; nt < 8; nt++) {
            int r0 = mBase + warp_m * 32 + mt * 16 + (lane >> 2);
            int cc = nBase + warp_n * 64 + nt * 8 + 2 * (lane & 3);
            float v[4];
#pragma unroll
            for (int j = 0; j < 4; j++)
                v[j] = (65536.f * (float)acc1[mt][nt][j] + 256.f * (float)accX[mt][nt][j]) * s;
#pragma unroll
            for (int half = 0; half < 2; half++) {
                int r = r0 + half * 8;
#pragma unroll
                for (int q = 0; q < 2; q++) {
                    int col = cc + q;
                    float val = v[half * 2 + q];
                    size_t o = (size_t)r * ldc + col;
                    if (mode == 1) {
                        val += ALPHA_F * Add[o];
                    } else if (mode == 2) {
                        int ic = col & 1023;
                        val += ALPHA_F * Add[(size_t)r * 1024 + ic];
                        if (col >= 1024)
                            val *= (1.f - exp2f(-(float)(5 + (ic >> 6))));
                    }
                    C[o] = val;
                }
            }
        }
    }
}

// ---------------- attention per (b,n,h) ----------------
__global__ void __launch_bounds__(256) attn_kernel(
    const float* __restrict__ Yqk, const float* __restrict__ vsum,
    float* __restrict__ O)
{
    __shared__ float rq[1792], rk[1792], qs[1792], ks[1792], vs[1792], sc[784];

    const int id = blockIdx.x;
    const int h  = id % HH;
    const int bn = id / HH;
    const int n  = bn & (NH - 1);
    const int b  = bn >> 4;
    const int tid = threadIdx.x;

    for (int i = tid; i < 1792; i += 256) {
        int xr = i >> 6, d = i & 63;
        size_t rowbase = ((size_t)b * (HH * WW) + h * WW + xr);
        size_t gq = rowbase * 2048 + n * DH + d;
        rq[i] = Yqk[gq];
        rk[i] = Yqk[gq + 1024];
        vs[i] = vsum[(((size_t)b * WW + xr) * HID) + n * DH + d];
    }
    __syncthreads();

    for (int i = tid; i < 1792; i += 256) {
        int xr = i >> 6, d = i & 63;
        int j = d & 15;
        float ang = (d < 32 ? (float)h : (float)xr) * expf(-(float)j * LN1E4_16);
        float s, c;
        sincosf(ang, &s, &c);
        bool second = (d & 16) != 0;
        int partner = second ? i - 16 : i + 16;
        float sgn = second ? 1.f : -1.f;
        qs[i] = rq[i] * c + sgn * rq[partner] * s;
        ks[i] = rk[i] * c + sgn * rk[partner] * s;
    }
    __syncthreads();

    for (int i = tid; i < 784; i += 256) {
        int xr = i / WW, z = i % WW;
        const float* qp = &qs[xr * DH];
        const float* kp = &ks[z * DH];
        float accv = 0.f;
#pragma unroll 16
        for (int d = 0; d < DH; d++) accv += qp[d] * kp[d];
        sc[i] = accv;
    }
    __syncthreads();

    for (int i = tid; i < 1792; i += 256) {
        int w = i >> 6, d = i & 63;
        float accv = 0.f;
#pragma unroll
        for (int y = 0; y < WW; y++) accv += sc[w * WW + y] * vs[y * DH + d];
        O[(size_t)bn * GSZ + h * (WW * DH) + i] = accv;
    }
}

// ---------------- groupnorm stats (sum, sumsq, min, max) ----------------
__global__ void __launch_bounds__(256) stats_kernel(const float* __restrict__ O)
{
    int bn = blockIdx.x;
    const float* p = O + (size_t)bn * GSZ;
    float s = 0.f, ss = 0.f, mn = 3.4e38f, mx = -3.4e38f;
    for (int i = threadIdx.x; i < GSZ; i += 256) {
        float v = p[i];
        s += v; ss += v * v;
        mn = fminf(mn, v); mx = fmaxf(mx, v);
    }
#pragma unroll
    for (int o = 16; o > 0; o >>= 1) {
        s  += __shfl_down_sync(0xffffffffu, s,  o);
        ss += __shfl_down_sync(0xffffffffu, ss, o);
        mn = fminf(mn, __shfl_down_sync(0xffffffffu, mn, o));
        mx = fmaxf(mx, __shfl_down_sync(0xffffffffu, mx, o));
    }
    __shared__ float sh[32];
    int w = threadIdx.x >> 5, l = threadIdx.x & 31;
    if (l == 0) { sh[w] = s; sh[8 + w] = ss; sh[16 + w] = mn; sh[24 + w] = mx; }
    __syncthreads();
    if (threadIdx.x == 0) {
        float a = 0.f, b2 = 0.f, m1 = sh[16], m2 = sh[24];
#pragma unroll
        for (int i = 0; i < 8; i++) {
            a += sh[i]; b2 += sh[8 + i];
            m1 = fminf(m1, sh[16 + i]); m2 = fmaxf(m2, sh[24 + i]);
        }
        g_stats4[bn] = make_float4(a, b2, m1, m2);
    }
}

// ---------------- combine: per-group affine + global Z scale ----------------
__global__ void combine_kernel(const float* __restrict__ gnw, const float* __restrict__ gnb)
{
    int bn = threadIdx.x;   // 512 threads
    float4 st = g_stats4[bn];
    float inv = 1.f / (float)GSZ;
    float mu = st.x * inv;
    float var = st.y * inv - mu * mu;
    float rstd = rsqrtf(var + 1e-5f);
    int n = bn & (NH - 1);
    float a = rstd * gnw[n];
    float c = gnb[n] - mu * a;
    g_ac[bn] = make_float2(a, c);
    float zm = fmaxf(fabsf(a * st.w + c), fabsf(a * st.z + c));
#pragma unroll
    for (int o = 16; o > 0; o >>= 1) zm = fmaxf(zm, __shfl_xor_sync(0xffffffffu, zm, o));
    __shared__ float sh[16];
    if ((threadIdx.x & 31) == 0) sh[threadIdx.x >> 5] = zm;
    __syncthreads();
    if (threadIdx.x == 0) {
        float m = sh[0];
#pragma unroll
        for (int i = 1; i < 16; i++) m = fmaxf(m, sh[i]);
        g_sbits[4] = __float_as_uint(m);
    }
}

// ---------------- normalize + transpose + quant-split Z ----------------
__global__ void norm_kernel(const float* __restrict__ O, int8_t* __restrict__ Zq)
{
    size_t i4 = ((size_t)blockIdx.x * 256 + threadIdx.x) * 4;
    int bn = (int)(i4 / GSZ);
    int rem = (int)(i4 % GSZ);
    int n = bn & (NH - 1), b = bn >> 4;
    int h = rem / (WW * DH);
    int rem2 = rem % (WW * DH);
    int w = rem2 >> 6, d = rem2 & 63;
    float2 ac = g_ac[bn];
    float rcp = QDIV / slot_max(4);
    float4 o = *(const float4*)(O + i4);
    int h0, l0, h1, l1, h2, l2, h3, l3;
    quant2((ac.x * o.x + ac.y) * rcp, h0, l0);
    quant2((ac.x * o.y + ac.y) * rcp, h1, l1);
    quant2((ac.x * o.z + ac.y) * rcp, h2, l2);
    quant2((ac.x * o.w + ac.y) * rcp, h3, l3);
    size_t zo = ((size_t)b * (HH * WW) + h * WW + w) * 2048 + n * DH + d;
    *(char4*)(Zq + zo)        = make_char4((char)h0, (char)h1, (char)h2, (char)h3);
    *(char4*)(Zq + zo + 1024) = make_char4((char)l0, (char)l1, (char)l2, (char)l3);
}

// ---------------- launch ----------------
extern "C" void kernel_launch(void* const* d_in, const int* in_sizes, int n_in,
                              void* d_out, int out_size)
{
    const float* x    = (const float*)d_in[0];
    const float* img  = (const float*)d_in[1];
    const float* qkvw = (const float*)d_in[2];
    const float* ow   = (const float*)d_in[3];
    const float* gnw  = (const float*)d_in[4];
    const float* gnb  = (const float*)d_in[5];
    float* out = (float*)d_out;

    float *Yqk, *xs, *is_, *vs, *O;
    int8_t *xq, *xsq, *Zq, *Wq, *Oq;
    cudaGetSymbolAddress((void**)&Yqk, g_Yqk);
    cudaGetSymbolAddress((void**)&xs,  g_xsum);
    cudaGetSymbolAddress((void**)&is_, g_isum);
    cudaGetSymbolAddress((void**)&vs,  g_vsum);
    cudaGetSymbolAddress((void**)&O,   g_O);
    cudaGetSymbolAddress((void**)&xq,  g_xq);
    cudaGetSymbolAddress((void**)&xsq, g_xsq);
    cudaGetSymbolAddress((void**)&Zq,  g_Zq);
    cudaGetSymbolAddress((void**)&Wq,  g_Wq);
    cudaGetSymbolAddress((void**)&Oq,  g_Oq);

    cudaFuncSetAttribute(gemm_s8, cudaFuncAttributeMaxDynamicSharedMemorySize, GSMEM);

    // 1-5: scales, sums, quantized operands
    zero_kernel<<<1, 32>>>();
    absmax_kernel<<<384, 256>>>(qkvw, 3072 * 1024 / 4, 1);
    sumhw_kernel<<<3584, 256>>>(x, img, xs, is_);            // also slot0 (x), slot3 (xsum)
    transcvt_kernel<<<dim3(96, 32), 256>>>(qkvw, 3072, 1, Wq, 1);
    quantsplit_kernel<<<ROWS, 256>>>(x, xq, 0);

    // 6: Yqk = x @ [Wq|Wk] with fused alpha*img add + gamma  (M=25088, N=2048)
    gemm_s8<<<dim3(16, 196), 256, GSMEM>>>(xq, Wq, Yqk, img, 2048, 0, 1, 2);

    // 7-9: o_w quant, xsum quant
    absmax_kernel<<<256, 256>>>(ow, 1024 * 1024 / 4, 2);
    transcvt_kernel<<<dim3(32, 32), 256>>>(ow, 1024, 0, Oq, 2);
    quantsplit_kernel<<<B_ * WW, 256>>>(xs, xsq, 3);

    // 10: vsum = xsum @ Wv + ALPHA*isum  (M=896, N=1024; Wv rows [2048,3072))
    gemm_s8<<<dim3(8, 7), 256, GSMEM>>>(xsq, Wq + (size_t)2048 * 2048, vs, is_, 1024, 3, 1, 1);

    // 11: attention
    attn_kernel<<<BNG * HH, 256>>>(Yqk, vs, O);

    // 12-14: groupnorm + quantized Z
    stats_kernel<<<BNG, 256>>>(O);
    combine_kernel<<<1, 512>>>(gnw, gnb);
    norm_kernel<<<(int)(((size_t)BNG * GSZ) / 1024), 256>>>(O, Zq);

    // 15: out = Z @ o_w  (M=25088, N=1024)
    gemm_s8<<<dim3(8, 196), 256, GSMEM>>>(Zq, Oq, out, nullptr, 1024, 4, 2, 0);
}

// round 7
// speedup vs baseline: 2.7504x; 2.2107x over previous
#include <cuda_runtime.h>
#include <math.h>
#include <stdint.h>

// ---------------- problem constants ----------------
#define B_    32
#define HH    28
#define WW    28
#define HID   1024
#define NH    16
#define DH    64
#define ROWS  25088
#define BNG   512
#define GSZ   50176

#define ALPHA_F 0.0828476643f
#define LN1E4_16 0.5756462732485114f

// ---------------- scratch ----------------
__device__ float g_Yqk[(size_t)ROWS * 2048];
__device__ float g_xt[(size_t)ROWS * HID];      // tf32-rounded x
__device__ float g_xsum[B_ * WW * HID];         // tf32-rounded sum_h x
__device__ float g_isum[B_ * WW * HID];
__device__ float g_vsum[B_ * WW * HID];
__device__ float g_O[(size_t)BNG * GSZ];
__device__ float g_Zt[(size_t)ROWS * HID];      // tf32-rounded normalized/transposed
__device__ float g_Wt[(size_t)3072 * HID];      // transposed tf32 qkv_w ([q|k|v] rows)
__device__ float g_Ot[(size_t)1024 * HID];      // transposed tf32 o_w
__device__ float2 g_stats2[BNG];

// ---------------- helpers ----------------
__device__ __forceinline__ uint32_t smem_u32(const void* p) {
    uint32_t a;
    asm("{ .reg .u64 t; cvta.to.shared.u64 t, %1; cvt.u32.u64 %0, t; }" : "=r"(a) : "l"(p));
    return a;
}
#define SWZ(x) ((x) ^ (((x) >> 3) & 0x70))

__device__ __forceinline__ float tf32r(float x) {
    uint32_t u;
    asm("cvt.rna.tf32.f32 %0, %1;" : "=r"(u) : "f"(x));
    return __uint_as_float(u);
}
__device__ __forceinline__ void cp16(uint32_t saddr, const void* g) {
    asm volatile("cp.async.cg.shared.global [%0], [%1], 16;" :: "r"(saddr), "l"(g));
}
__device__ __forceinline__ void cp_commit() {
    asm volatile("cp.async.commit_group;" ::: "memory");
}
template <int N>
__device__ __forceinline__ void cp_waitg() {
    asm volatile("cp.async.wait_group %0;" :: "n"(N) : "memory");
}
__device__ __forceinline__ void ldm_x4(uint32_t& r0, uint32_t& r1, uint32_t& r2, uint32_t& r3,
                                       uint32_t addr) {
    asm volatile("ldmatrix.sync.aligned.m8n8.x4.shared.b16 {%0,%1,%2,%3}, [%4];"
                 : "=r"(r0), "=r"(r1), "=r"(r2), "=r"(r3) : "r"(addr));
}
__device__ __forceinline__ void mma_tf32(float* d, const uint32_t* a, const uint32_t* b) {
    asm volatile(
        "mma.sync.aligned.m16n8k8.row.col.f32.tf32.tf32.f32 "
        "{%0,%1,%2,%3}, {%4,%5,%6,%7}, {%8,%9}, {%0,%1,%2,%3};"
        : "+f"(d[0]), "+f"(d[1]), "+f"(d[2]), "+f"(d[3])
        : "r"(a[0]), "r"(a[1]), "r"(a[2]), "r"(a[3]), "r"(b[0]), "r"(b[1]));
}

// ---------------- x -> tf32-rounded copy ----------------
__global__ void cvtx_kernel(const float* __restrict__ X, float* __restrict__ Xt) {
    size_t i = ((size_t)blockIdx.x * 256 + threadIdx.x) * 4;
    float4 v = *(const float4*)(X + i);
    v.x = tf32r(v.x); v.y = tf32r(v.y); v.z = tf32r(v.z); v.w = tf32r(v.w);
    *(float4*)(Xt + i) = v;
}

// ---------------- weight transpose + tf32 round ----------------
__global__ void transcvt_kernel(const float* __restrict__ W, int ldw, int perm,
                                float* __restrict__ T)
{
    __shared__ float t[32][33];
    const int nb = blockIdx.x * 32, kb = blockIdx.y * 32;
    const int tx = threadIdx.x & 31, ty = threadIdx.x >> 5;
    int n = nb + tx;
    int sc = perm ? (n < 1024 ? n : (n < 2048 ? n + 1024 : n - 1024)) : n;
#pragma unroll
    for (int i = 0; i < 4; i++)
        t[ty + 8 * i][tx] = W[(size_t)(kb + ty + 8 * i) * ldw + sc];
    __syncthreads();
#pragma unroll
    for (int i = 0; i < 4; i++) {
        int nn = nb + ty + 8 * i, kk = kb + tx;
        T[(size_t)nn * HID + kk] = tf32r(t[tx][ty + 8 * i]);
    }
}

// ---------------- sum over H of x and img ----------------
__global__ void sumhw_kernel(const float* __restrict__ x, const float* __restrict__ img,
                             float* __restrict__ xs, float* __restrict__ is_)
{
    int idx = blockIdx.x * 256 + threadIdx.x;
    int r = idx >> 10;
    int b = r / WW, w = r % WW;
    size_t base = ((size_t)b * (HH * WW) + w) * HID + (idx & 1023);
    float s1 = 0.f, s2 = 0.f;
#pragma unroll 4
    for (int h = 0; h < HH; h++) {
        s1 += x[base];
        s2 += img[base];
        base += (size_t)WW * HID;
    }
    xs[idx] = tf32r(s1);
    is_[idx] = s2;
}

// ---------------- TF32 GEMM: C[M,N] = A[M,1024] @ Bt[N,1024]^T ----------------
// Tiles 128x128x32(K). 3-stage cp.async pipeline, 8 warps (warp tile 32x64).
// mode 0: plain. 1: += ALPHA*Add (ldc layout). 2: qk-fused (+ALPHA*img, gamma for col>=1024).
#define TOFF_B 16384
#define TSTAGE 32768
#define TSMEM  (3 * TSTAGE)    // 98304

__global__ void __launch_bounds__(256, 1) gemm_tf32(
    const float* __restrict__ A, const float* __restrict__ Bt,
    float* __restrict__ C, const float* __restrict__ Add,
    int ldc, int mode)
{
    extern __shared__ char smem[];
    const uint32_t sb = smem_u32(smem);
    const int tid = threadIdx.x, lane = tid & 31, wid = tid >> 5;
    const int warp_m = wid & 3, warp_n = wid >> 2;
    const int mBase = blockIdx.y * 128, nBase = blockIdx.x * 128;

    float acc[2][8][4];
#pragma unroll
    for (int m = 0; m < 2; m++)
#pragma unroll
        for (int n = 0; n < 8; n++)
#pragma unroll
            for (int j = 0; j < 4; j++) acc[m][n][j] = 0.f;

    // loader: A tile 128x32 f32 = 1024 16B chunks; same for B; 4 each per thread
    auto load_stage = [&](int c, int s) {
        uint32_t st = sb + s * TSTAGE;
        int k0 = c * 32;
#pragma unroll
        for (int i = 0; i < 4; i++) {
            int q = tid + i * 256;            // 0..1023
            int row = q >> 3, cc = q & 7;
            uint32_t so = SWZ(row * 128 + cc * 16);
            cp16(st + so,           A  + (size_t)(mBase + row) * HID + k0 + cc * 4);
            cp16(st + TOFF_B + so,  Bt + (size_t)(nBase + row) * HID + k0 + cc * 4);
        }
        cp_commit();
    };

    load_stage(0, 0);
    load_stage(1, 1);

    const int arow = (lane & 15);
    const int chi  = (lane & 16) ? 16 : 0;

    for (int c = 0; c < 32; c++) {
        if (c == 31) cp_waitg<0>(); else cp_waitg<1>();
        __syncthreads();
        if (c + 2 < 32) load_stage(c + 2, (c + 2) % 3);

        const uint32_t st = sb + (c % 3) * TSTAGE;
#pragma unroll
        for (int ks = 0; ks < 4; ks++) {
            const int coloff = ks * 32 + chi;
            uint32_t a[2][4];
#pragma unroll
            for (int mt = 0; mt < 2; mt++) {
                int row = warp_m * 32 + mt * 16 + arow;
                ldm_x4(a[mt][0], a[mt][1], a[mt][2], a[mt][3],
                       st + SWZ(row * 128 + coloff));
            }
#pragma unroll
            for (int np = 0; np < 4; np++) {
                int rn = warp_n * 64 + np * 16 + arow;
                uint32_t r0, r1, r2, r3;
                ldm_x4(r0, r1, r2, r3, st + TOFF_B + SWZ(rn * 128 + coloff));
                uint32_t be[2] = {r0, r2}, bo[2] = {r1, r3};
#pragma unroll
                for (int mt = 0; mt < 2; mt++) {
                    mma_tf32(acc[mt][2 * np],     a[mt], be);
                    mma_tf32(acc[mt][2 * np + 1], a[mt], bo);
                }
            }
        }
    }

#pragma unroll
    for (int mt = 0; mt < 2; mt++) {
#pragma unroll
        for (int nt = 0; nt < 8; nt++) {
            int r0 = mBase + warp_m * 32 + mt * 16 + (lane >> 2);
            int cc = nBase + warp_n * 64 + nt * 8 + 2 * (lane & 3);
#pragma unroll
            for (int half = 0; half < 2; half++) {
                int r = r0 + half * 8;
#pragma unroll
                for (int q = 0; q < 2; q++) {
                    int col = cc + q;
                    float val = acc[mt][nt][half * 2 + q];
                    size_t o = (size_t)r * ldc + col;
                    if (mode == 1) {
                        val += ALPHA_F * Add[o];
                    } else if (mode == 2) {
                        int ic = col & 1023;
                        val += ALPHA_F * Add[(size_t)r * 1024 + ic];
                        if (col >= 1024)
                            val *= (1.f - exp2f(-(float)(5 + (ic >> 6))));
                    }
                    C[o] = val;
                }
            }
        }
    }
}

// ---------------- attention per (b,n,h) ----------------
__global__ void __launch_bounds__(256) attn_kernel(
    const float* __restrict__ Yqk, const float* __restrict__ vsum,
    float* __restrict__ O)
{
    __shared__ float rq[1792], rk[1792], qs[1792], ks[1792], vs[1792], sc[784];

    const int id = blockIdx.x;
    const int h  = id % HH;
    const int bn = id / HH;
    const int n  = bn & (NH - 1);
    const int b  = bn >> 4;
    const int tid = threadIdx.x;

    for (int i = tid; i < 1792; i += 256) {
        int xr = i >> 6, d = i & 63;
        size_t rowbase = ((size_t)b * (HH * WW) + h * WW + xr);
        size_t gq = rowbase * 2048 + n * DH + d;
        rq[i] = Yqk[gq];
        rk[i] = Yqk[gq + 1024];
        vs[i] = vsum[(((size_t)b * WW + xr) * HID) + n * DH + d];
    }
    __syncthreads();

    for (int i = tid; i < 1792; i += 256) {
        int xr = i >> 6, d = i & 63;
        int j = d & 15;
        float ang = (d < 32 ? (float)h : (float)xr) * expf(-(float)j * LN1E4_16);
        float s, c;
        sincosf(ang, &s, &c);
        bool second = (d & 16) != 0;
        int partner = second ? i - 16 : i + 16;
        float sgn = second ? 1.f : -1.f;
        qs[i] = rq[i] * c + sgn * rq[partner] * s;
        ks[i] = rk[i] * c + sgn * rk[partner] * s;
    }
    __syncthreads();

    for (int i = tid; i < 784; i += 256) {
        int xr = i / WW, z = i % WW;
        const float* qp = &qs[xr * DH];
        const float* kp = &ks[z * DH];
        float accv = 0.f;
#pragma unroll 16
        for (int d = 0; d < DH; d++) accv += qp[d] * kp[d];
        sc[i] = accv;
    }
    __syncthreads();

    for (int i = tid; i < 1792; i += 256) {
        int w = i >> 6, d = i & 63;
        float accv = 0.f;
#pragma unroll
        for (int y = 0; y < WW; y++) accv += sc[w * WW + y] * vs[y * DH + d];
        O[(size_t)bn * GSZ + h * (WW * DH) + i] = accv;
    }
}

// ---------------- groupnorm stats ----------------
__global__ void __launch_bounds__(256) stats_kernel(const float* __restrict__ O)
{
    int bn = blockIdx.x;
    const float* p = O + (size_t)bn * GSZ;
    float s = 0.f, ss = 0.f;
    for (int i = threadIdx.x; i < GSZ; i += 256) {
        float v = p[i];
        s += v; ss += v * v;
    }
#pragma unroll
    for (int o = 16; o > 0; o >>= 1) {
        s  += __shfl_down_sync(0xffffffffu, s,  o);
        ss += __shfl_down_sync(0xffffffffu, ss, o);
    }
    __shared__ float sh[16];
    int w = threadIdx.x >> 5, l = threadIdx.x & 31;
    if (l == 0) { sh[w] = s; sh[8 + w] = ss; }
    __syncthreads();
    if (threadIdx.x == 0) {
        float a = 0.f, b2 = 0.f;
#pragma unroll
        for (int i = 0; i < 8; i++) { a += sh[i]; b2 += sh[8 + i]; }
        g_stats2[bn] = make_float2(a, b2);
    }
}

// ---------------- normalize + transpose -> tf32 Z ----------------
__global__ void norm_kernel(const float* __restrict__ O,
                            const float* __restrict__ gnw, const float* __restrict__ gnb,
                            float* __restrict__ Zt)
{
    size_t i4 = ((size_t)blockIdx.x * 256 + threadIdx.x) * 4;
    int bn = (int)(i4 / GSZ);
    int rem = (int)(i4 % GSZ);
    int n = bn & (NH - 1), b = bn >> 4;
    int h = rem / (WW * DH);
    int rem2 = rem % (WW * DH);
    int w = rem2 >> 6, d = rem2 & 63;
    float2 st = g_stats2[bn];
    float inv = 1.f / (float)GSZ;
    float mu  = st.x * inv;
    float var = st.y * inv - mu * mu;
    float a = rsqrtf(var + 1e-5f) * gnw[n];
    float cb = gnb[n] - mu * a;
    float4 o = *(const float4*)(O + i4);
    float4 z;
    z.x = tf32r(a * o.x + cb);
    z.y = tf32r(a * o.y + cb);
    z.z = tf32r(a * o.z + cb);
    z.w = tf32r(a * o.w + cb);
    size_t zo = ((size_t)b * (HH * WW) + h * WW + w) * HID + n * DH + d;
    *(float4*)(Zt + zo) = z;
}

// ---------------- launch ----------------
extern "C" void kernel_launch(void* const* d_in, const int* in_sizes, int n_in,
                              void* d_out, int out_size)
{
    const float* x    = (const float*)d_in[0];
    const float* img  = (const float*)d_in[1];
    const float* qkvw = (const float*)d_in[2];
    const float* ow   = (const float*)d_in[3];
    const float* gnw  = (const float*)d_in[4];
    const float* gnb  = (const float*)d_in[5];
    float* out = (float*)d_out;

    float *Yqk, *xt, *xs, *is_, *vs, *O, *Zt, *Wt, *Ot;
    cudaGetSymbolAddress((void**)&Yqk, g_Yqk);
    cudaGetSymbolAddress((void**)&xt,  g_xt);
    cudaGetSymbolAddress((void**)&xs,  g_xsum);
    cudaGetSymbolAddress((void**)&is_, g_isum);
    cudaGetSymbolAddress((void**)&vs,  g_vsum);
    cudaGetSymbolAddress((void**)&O,   g_O);
    cudaGetSymbolAddress((void**)&Zt,  g_Zt);
    cudaGetSymbolAddress((void**)&Wt,  g_Wt);
    cudaGetSymbolAddress((void**)&Ot,  g_Ot);

    cudaFuncSetAttribute(gemm_tf32, cudaFuncAttributeMaxDynamicSharedMemorySize, TSMEM);

    // prep: weights transpose+round, x round, sums
    transcvt_kernel<<<dim3(96, 32), 256>>>(qkvw, 3072, 1, Wt);
    transcvt_kernel<<<dim3(32, 32), 256>>>(ow,   1024, 0, Ot);
    cvtx_kernel<<<ROWS * HID / 1024, 256>>>(x, xt);
    sumhw_kernel<<<3584, 256>>>(x, img, xs, is_);

    // Yqk = x @ [Wq|Wk] with fused alpha*img + gamma  (M=25088, N=2048)
    gemm_tf32<<<dim3(16, 196), 256, TSMEM>>>(xt, Wt, Yqk, img, 2048, 2);

    // vsum = xsum @ Wv + ALPHA*isum  (M=896, N=1024; Wv rows [2048,3072))
    gemm_tf32<<<dim3(8, 7), 256, TSMEM>>>(xs, Wt + (size_t)2048 * HID, vs, is_, 1024, 1);

    // attention
    attn_kernel<<<BNG * HH, 256>>>(Yqk, vs, O);

    // groupnorm -> tf32 Z
    stats_kernel<<<BNG, 256>>>(O);
    norm_kernel<<<ROWS * HID / 1024, 256>>>(O, gnw, gnb, Zt);

    // out = Z @ o_w  (M=25088, N=1024)
    gemm_tf32<<<dim3(8, 196), 256, TSMEM>>>(Zt, Ot, out, nullptr, 1024, 0);
}

// round 8
// speedup vs baseline: 4.2664x; 1.5512x over previous
#include <cuda_runtime.h>
#include <math.h>
#include <stdint.h>

// ---------------- problem constants ----------------
#define B_    32
#define HH    28
#define WW    28
#define HID   1024
#define NH    16
#define DH    64
#define ROWS  25088
#define BNG   512
#define GSZ   50176

#define ALPHA_F 0.0828476643f
#define LN1E4_16 0.5756462732485114f

// ---------------- scratch ----------------
__device__ float g_Yqk[(size_t)ROWS * 2048];
__device__ float g_xt[(size_t)ROWS * HID];
__device__ float g_xsum[B_ * WW * HID];
__device__ float g_isum[B_ * WW * HID];
__device__ float g_vsum[B_ * WW * HID];
__device__ float g_O[(size_t)BNG * GSZ];
__device__ float g_Zt[(size_t)ROWS * HID];
__device__ float g_Wt[(size_t)3072 * HID];
__device__ float g_Ot[(size_t)1024 * HID];
__device__ float2 g_part[BNG * HH];
__device__ float2 g_ac[BNG];

// ---------------- helpers ----------------
__device__ __forceinline__ uint32_t smem_u32(const void* p) {
    uint32_t a;
    asm("{ .reg .u64 t; cvta.to.shared.u64 t, %1; cvt.u32.u64 %0, t; }" : "=r"(a) : "l"(p));
    return a;
}
#define SWZ(x) ((x) ^ (((x) >> 3) & 0x70))

__device__ __forceinline__ float tf32r(float x) {
    uint32_t u;
    asm("cvt.rna.tf32.f32 %0, %1;" : "=r"(u) : "f"(x));
    return __uint_as_float(u);
}
__device__ __forceinline__ void cp16(uint32_t saddr, const void* g) {
    asm volatile("cp.async.cg.shared.global [%0], [%1], 16;" :: "r"(saddr), "l"(g));
}
__device__ __forceinline__ void cp_commit() {
    asm volatile("cp.async.commit_group;" ::: "memory");
}
template <int N>
__device__ __forceinline__ void cp_waitg() {
    asm volatile("cp.async.wait_group %0;" :: "n"(N) : "memory");
}
__device__ __forceinline__ void ldm_x4(uint32_t& r0, uint32_t& r1, uint32_t& r2, uint32_t& r3,
                                       uint32_t addr) {
    asm volatile("ldmatrix.sync.aligned.m8n8.x4.shared.b16 {%0,%1,%2,%3}, [%4];"
                 : "=r"(r0), "=r"(r1), "=r"(r2), "=r"(r3) : "r"(addr));
}
__device__ __forceinline__ void mma_tf32(float* d, const uint32_t* a, const uint32_t* b) {
    asm volatile(
        "mma.sync.aligned.m16n8k8.row.col.f32.tf32.tf32.f32 "
        "{%0,%1,%2,%3}, {%4,%5,%6,%7}, {%8,%9}, {%0,%1,%2,%3};"
        : "+f"(d[0]), "+f"(d[1]), "+f"(d[2]), "+f"(d[3])
        : "r"(a[0]), "r"(a[1]), "r"(a[2]), "r"(a[3]), "r"(b[0]), "r"(b[1]));
}

// ---------------- x -> tf32-rounded copy ----------------
__global__ void cvtx_kernel(const float* __restrict__ X, float* __restrict__ Xt) {
    size_t i = ((size_t)blockIdx.x * 256 + threadIdx.x) * 4;
    float4 v = *(const float4*)(X + i);
    v.x = tf32r(v.x); v.y = tf32r(v.y); v.z = tf32r(v.z); v.w = tf32r(v.w);
    *(float4*)(Xt + i) = v;
}

// ---------------- weight transpose + tf32 round ----------------
__global__ void transcvt_kernel(const float* __restrict__ W, int ldw, int perm,
                                float* __restrict__ T)
{
    __shared__ float t[32][33];
    const int nb = blockIdx.x * 32, kb = blockIdx.y * 32;
    const int tx = threadIdx.x & 31, ty = threadIdx.x >> 5;
    int n = nb + tx;
    int sc = perm ? (n < 1024 ? n : (n < 2048 ? n + 1024 : n - 1024)) : n;
#pragma unroll
    for (int i = 0; i < 4; i++)
        t[ty + 8 * i][tx] = W[(size_t)(kb + ty + 8 * i) * ldw + sc];
    __syncthreads();
#pragma unroll
    for (int i = 0; i < 4; i++) {
        int nn = nb + ty + 8 * i, kk = kb + tx;
        T[(size_t)nn * HID + kk] = tf32r(t[tx][ty + 8 * i]);
    }
}

// ---------------- sum over H of x and img ----------------
__global__ void sumhw_kernel(const float* __restrict__ x, const float* __restrict__ img,
                             float* __restrict__ xs, float* __restrict__ is_)
{
    int idx = blockIdx.x * 256 + threadIdx.x;
    int r = idx >> 10;
    int b = r / WW, w = r % WW;
    size_t base = ((size_t)b * (HH * WW) + w) * HID + (idx & 1023);
    float s1 = 0.f, s2 = 0.f;
#pragma unroll 4
    for (int h = 0; h < HH; h++) {
        s1 += x[base];
        s2 += img[base];
        base += (size_t)WW * HID;
    }
    xs[idx] = tf32r(s1);
    is_[idx] = s2;
}

// ---------------- TF32 GEMM: C[M,N] = A[M,1024] @ Bt[N,1024]^T ----------------
#define TOFF_B 16384
#define TSTAGE 32768
#define TSMEM  (3 * TSTAGE)    // 98304

__global__ void __launch_bounds__(256, 2) gemm_tf32(
    const float* __restrict__ A, const float* __restrict__ Bt,
    float* __restrict__ C, const float* __restrict__ Add,
    int ldc, int mode)
{
    extern __shared__ char smem[];
    const uint32_t sb = smem_u32(smem);
    const int tid = threadIdx.x, lane = tid & 31, wid = tid >> 5;
    const int warp_m = wid & 3, warp_n = wid >> 2;
    const int mBase = blockIdx.y * 128, nBase = blockIdx.x * 128;

    float acc[2][8][4];
#pragma unroll
    for (int m = 0; m < 2; m++)
#pragma unroll
        for (int n = 0; n < 8; n++)
#pragma unroll
            for (int j = 0; j < 4; j++) acc[m][n][j] = 0.f;

    auto load_stage = [&](int c, int s) {
        uint32_t st = sb + s * TSTAGE;
        int k0 = c * 32;
#pragma unroll
        for (int i = 0; i < 4; i++) {
            int q = tid + i * 256;
            int row = q >> 3, cc = q & 7;
            uint32_t so = SWZ(row * 128 + cc * 16);
            cp16(st + so,          A  + (size_t)(mBase + row) * HID + k0 + cc * 4);
            cp16(st + TOFF_B + so, Bt + (size_t)(nBase + row) * HID + k0 + cc * 4);
        }
        cp_commit();
    };

    load_stage(0, 0);
    load_stage(1, 1);

    const int arow = (lane & 15);
    const int chi  = (lane & 16) ? 16 : 0;

    for (int c = 0; c < 32; c++) {
        if (c == 31) cp_waitg<0>(); else cp_waitg<1>();
        __syncthreads();
        if (c + 2 < 32) load_stage(c + 2, (c + 2) % 3);

        const uint32_t st = sb + (c % 3) * TSTAGE;
#pragma unroll
        for (int ks = 0; ks < 4; ks++) {
            const int coloff = ks * 32 + chi;
            uint32_t a[2][4];
#pragma unroll
            for (int mt = 0; mt < 2; mt++) {
                int row = warp_m * 32 + mt * 16 + arow;
                ldm_x4(a[mt][0], a[mt][1], a[mt][2], a[mt][3],
                       st + SWZ(row * 128 + coloff));
            }
#pragma unroll
            for (int np = 0; np < 4; np++) {
                int rn = warp_n * 64 + np * 16 + arow;
                uint32_t r0, r1, r2, r3;
                ldm_x4(r0, r1, r2, r3, st + TOFF_B + SWZ(rn * 128 + coloff));
                uint32_t be[2] = {r0, r2}, bo[2] = {r1, r3};
#pragma unroll
                for (int mt = 0; mt < 2; mt++) {
                    mma_tf32(acc[mt][2 * np],     a[mt], be);
                    mma_tf32(acc[mt][2 * np + 1], a[mt], bo);
                }
            }
        }
    }

#pragma unroll
    for (int mt = 0; mt < 2; mt++) {
#pragma unroll
        for (int nt = 0; nt < 8; nt++) {
            int r0 = mBase + warp_m * 32 + mt * 16 + (lane >> 2);
            int cc = nBase + warp_n * 64 + nt * 8 + 2 * (lane & 3);
#pragma unroll
            for (int half = 0; half < 2; half++) {
                int r = r0 + half * 8;
#pragma unroll
                for (int q = 0; q < 2; q++) {
                    int col = cc + q;
                    float val = acc[mt][nt][half * 2 + q];
                    size_t o = (size_t)r * ldc + col;
                    if (mode == 1) {
                        val += ALPHA_F * Add[o];
                    } else if (mode == 2) {
                        int ic = col & 1023;
                        val += ALPHA_F * Add[(size_t)r * 1024 + ic];
                        if (col >= 1024)
                            val *= (1.f - exp2f(-(float)(5 + (ic >> 6))));
                    }
                    C[o] = val;
                }
            }
        }
    }
}

// ---------------- attention per (b,n,h), register-tiled ----------------
#define RS 65   // padded row stride for 64-wide arrays
#define SS 29   // padded row stride for score rows

__global__ void __launch_bounds__(256) attn_kernel(
    const float* __restrict__ Yqk, const float* __restrict__ vsum,
    float* __restrict__ O, float2* __restrict__ part)
{
    __shared__ float rq[28 * RS], rk[28 * RS], qs[28 * RS], ks[28 * RS], vs[28 * RS];
    __shared__ float sc[28 * SS];
    __shared__ float shred[16];

    const int id = blockIdx.x;
    const int h  = id % HH;
    const int bn = id / HH;
    const int n  = bn & (NH - 1);
    const int b  = bn >> 4;
    const int tid = threadIdx.x;

    // load
    for (int i = tid; i < 1792; i += 256) {
        int xr = i >> 6, d = i & 63;
        size_t rowbase = ((size_t)b * (HH * WW) + h * WW + xr);
        size_t gq = rowbase * 2048 + n * DH + d;
        rq[xr * RS + d] = Yqk[gq];
        rk[xr * RS + d] = Yqk[gq + 1024];
        vs[xr * RS + d] = vsum[(((size_t)b * WW + xr) * HID) + n * DH + d];
    }
    __syncthreads();

    // axial rope
    for (int i = tid; i < 1792; i += 256) {
        int xr = i >> 6, d = i & 63;
        int j = d & 15;
        float ang = (d < 32 ? (float)h : (float)xr) * expf(-(float)j * LN1E4_16);
        float s, c;
        sincosf(ang, &s, &c);
        bool second = (d & 16) != 0;
        int pd = second ? d - 16 : d + 16;
        float sgn = second ? 1.f : -1.f;
        qs[xr * RS + d] = rq[xr * RS + d] * c + sgn * rq[xr * RS + pd] * s;
        ks[xr * RS + d] = rk[xr * RS + d] * c + sgn * rk[xr * RS + pd] * s;
    }
    __syncthreads();

    // scores: 2x2 tiles, 196 threads
    if (tid < 196) {
        int ti = tid / 14, tj = tid % 14;
        const float* q0 = qs + (2 * ti) * RS;
        const float* q1 = q0 + RS;
        const float* k0 = ks + (2 * tj) * RS;
        const float* k1 = k0 + RS;
        float a00 = 0.f, a01 = 0.f, a10 = 0.f, a11 = 0.f;
#pragma unroll 8
        for (int d = 0; d < 64; d++) {
            float qa = q0[d], qb = q1[d], ka = k0[d], kb = k1[d];
            a00 += qa * ka; a01 += qa * kb;
            a10 += qb * ka; a11 += qb * kb;
        }
        int r0 = 2 * ti, c0 = 2 * tj;
        sc[r0 * SS + c0] = a00;       sc[r0 * SS + c0 + 1] = a01;
        sc[(r0 + 1) * SS + c0] = a10; sc[(r0 + 1) * SS + c0 + 1] = a11;
    }
    __syncthreads();

    // out: 2(w) x 4(d) tiles, 224 threads; accumulate groupnorm partials
    float lsum = 0.f, lss = 0.f;
    if (tid < 224) {
        int wi = tid >> 4, di = tid & 15;
        int w0 = 2 * wi, d0 = 4 * di;
        float o0[4] = {0.f, 0.f, 0.f, 0.f};
        float o1[4] = {0.f, 0.f, 0.f, 0.f};
        const float* s0p = sc + w0 * SS;
        const float* s1p = s0p + SS;
#pragma unroll 4
        for (int y = 0; y < 28; y++) {
            float s0 = s0p[y], s1 = s1p[y];
            const float* vp = vs + y * RS + d0;
#pragma unroll
            for (int j = 0; j < 4; j++) {
                float v = vp[j];
                o0[j] += s0 * v;
                o1[j] += s1 * v;
            }
        }
        size_t base = (size_t)bn * GSZ + (size_t)h * 1792;
#pragma unroll
        for (int j = 0; j < 4; j++) { lsum += o0[j] + o1[j]; lss += o0[j] * o0[j] + o1[j] * o1[j]; }
        *(float4*)(O + base + w0 * 64 + d0)       = make_float4(o0[0], o0[1], o0[2], o0[3]);
        *(float4*)(O + base + (w0 + 1) * 64 + d0) = make_float4(o1[0], o1[1], o1[2], o1[3]);
    }
    // block reduce partial stats
#pragma unroll
    for (int o = 16; o > 0; o >>= 1) {
        lsum += __shfl_down_sync(0xffffffffu, lsum, o);
        lss  += __shfl_down_sync(0xffffffffu, lss,  o);
    }
    int w = tid >> 5, l = tid & 31;
    if (l == 0) { shred[w] = lsum; shred[8 + w] = lss; }
    __syncthreads();
    if (tid == 0) {
        float a = 0.f, b2 = 0.f;
#pragma unroll
        for (int i = 0; i < 8; i++) { a += shred[i]; b2 += shred[8 + i]; }
        part[bn * HH + h] = make_float2(a, b2);
    }
}

// ---------------- combine partials -> per-group affine ----------------
__global__ void combine_kernel(const float2* __restrict__ part,
                               const float* __restrict__ gnw, const float* __restrict__ gnb)
{
    int bn = threadIdx.x;   // 512
    float s = 0.f, ss = 0.f;
#pragma unroll
    for (int h = 0; h < HH; h++) {
        float2 p = part[bn * HH + h];
        s += p.x; ss += p.y;
    }
    float inv = 1.f / (float)GSZ;
    float mu = s * inv;
    float var = ss * inv - mu * mu;
    float rstd = rsqrtf(var + 1e-5f);
    int n = bn & (NH - 1);
    float a = rstd * gnw[n];
    g_ac[bn] = make_float2(a, gnb[n] - mu * a);
}

// ---------------- normalize + transpose -> tf32 Z ----------------
__global__ void norm_kernel(const float* __restrict__ O, float* __restrict__ Zt)
{
    size_t i4 = ((size_t)blockIdx.x * 256 + threadIdx.x) * 4;
    int bn = (int)(i4 / GSZ);
    int rem = (int)(i4 % GSZ);
    int n = bn & (NH - 1), b = bn >> 4;
    int h = rem / (WW * DH);
    int rem2 = rem % (WW * DH);
    int w = rem2 >> 6, d = rem2 & 63;
    float2 ac = g_ac[bn];
    float4 o = *(const float4*)(O + i4);
    float4 z;
    z.x = tf32r(ac.x * o.x + ac.y);
    z.y = tf32r(ac.x * o.y + ac.y);
    z.z = tf32r(ac.x * o.z + ac.y);
    z.w = tf32r(ac.x * o.w + ac.y);
    size_t zo = ((size_t)b * (HH * WW) + h * WW + w) * HID + n * DH + d;
    *(float4*)(Zt + zo) = z;
}

// ---------------- launch ----------------
extern "C" void kernel_launch(void* const* d_in, const int* in_sizes, int n_in,
                              void* d_out, int out_size)
{
    const float* x    = (const float*)d_in[0];
    const float* img  = (const float*)d_in[1];
    const float* qkvw = (const float*)d_in[2];
    const float* ow   = (const float*)d_in[3];
    const float* gnw  = (const float*)d_in[4];
    const float* gnb  = (const float*)d_in[5];
    float* out = (float*)d_out;

    float *Yqk, *xt, *xs, *is_, *vs, *O, *Zt, *Wt, *Ot;
    float2 *part;
    cudaGetSymbolAddress((void**)&Yqk, g_Yqk);
    cudaGetSymbolAddress((void**)&xt,  g_xt);
    cudaGetSymbolAddress((void**)&xs,  g_xsum);
    cudaGetSymbolAddress((void**)&is_, g_isum);
    cudaGetSymbolAddress((void**)&vs,  g_vsum);
    cudaGetSymbolAddress((void**)&O,   g_O);
    cudaGetSymbolAddress((void**)&Zt,  g_Zt);
    cudaGetSymbolAddress((void**)&Wt,  g_Wt);
    cudaGetSymbolAddress((void**)&Ot,  g_Ot);
    cudaGetSymbolAddress((void**)&part, g_part);

    cudaFuncSetAttribute(gemm_tf32, cudaFuncAttributeMaxDynamicSharedMemorySize, TSMEM);

    transcvt_kernel<<<dim3(96, 32), 256>>>(qkvw, 3072, 1, Wt);
    transcvt_kernel<<<dim3(32, 32), 256>>>(ow,   1024, 0, Ot);
    cvtx_kernel<<<ROWS * HID / 1024, 256>>>(x, xt);
    sumhw_kernel<<<3584, 256>>>(x, img, xs, is_);

    // Yqk = x @ [Wq|Wk] + fused alpha*img + gamma
    gemm_tf32<<<dim3(16, 196), 256, TSMEM>>>(xt, Wt, Yqk, img, 2048, 2);

    // vsum = xsum @ Wv + ALPHA*isum
    gemm_tf32<<<dim3(8, 7), 256, TSMEM>>>(xs, Wt + (size_t)2048 * HID, vs, is_, 1024, 1);

    // attention (+ groupnorm partials)
    attn_kernel<<<BNG * HH, 256>>>(Yqk, vs, O, part);

    // groupnorm combine + normalize
    combine_kernel<<<1, 512>>>(part, gnw, gnb);
    norm_kernel<<<ROWS * HID / 1024, 256>>>(O, Zt);

    // out = Z @ o_w
    gemm_tf32<<<dim3(8, 196), 256, TSMEM>>>(Zt, Ot, out, nullptr, 1024, 0);
}

// round 11
// speedup vs baseline: 6.5539x; 1.5362x over previous
#include <cuda_runtime.h>
#include <cuda_fp16.h>
#include <math.h>
#include <stdint.h>

// ---------------- problem constants ----------------
#define B_    32
#define HH    28
#define WW    28
#define HID   1024
#define NH    16
#define DH    64
#define ROWS  25088
#define BNG   512
#define GSZ   50176

#define ALPHA_F 0.0828476643f
#define LN1E4_16 0.5756462732485114f

// ---------------- scratch ----------------
__device__ float g_Yqk[(size_t)ROWS * 2048];
__device__ __half g_xh[(size_t)ROWS * HID];
__device__ __half g_xsh[B_ * WW * HID];
__device__ float g_isum[B_ * WW * HID];
__device__ float g_vsum[B_ * WW * HID];
__device__ float g_O[(size_t)BNG * GSZ];
__device__ __half g_Zt[(size_t)ROWS * HID];
__device__ __half g_Wt[(size_t)3072 * HID];
__device__ __half g_Ot[(size_t)1024 * HID];
__device__ float2 g_part[BNG * HH];
__device__ float2 g_ac[BNG];

// ---------------- helpers ----------------
__device__ __forceinline__ uint32_t smem_u32(const void* p) {
    uint32_t a;
    asm("{ .reg .u64 t; cvta.to.shared.u64 t, %1; cvt.u32.u64 %0, t; }" : "=r"(a) : "l"(p));
    return a;
}
#define SWZ(x) ((x) ^ (((x) >> 3) & 0x70))

__device__ __forceinline__ void cp16(uint32_t saddr, const void* g) {
    asm volatile("cp.async.cg.shared.global [%0], [%1], 16;" :: "r"(saddr), "l"(g));
}
__device__ __forceinline__ void cp_commit() {
    asm volatile("cp.async.commit_group;" ::: "memory");
}
template <int N>
__device__ __forceinline__ void cp_waitg() {
    asm volatile("cp.async.wait_group %0;" :: "n"(N) : "memory");
}
__device__ __forceinline__ void ldm_x4(uint32_t& r0, uint32_t& r1, uint32_t& r2, uint32_t& r3,
                                       uint32_t addr) {
    asm volatile("ldmatrix.sync.aligned.m8n8.x4.shared.b16 {%0,%1,%2,%3}, [%4];"
                 : "=r"(r0), "=r"(r1), "=r"(r2), "=r"(r3) : "r"(addr));
}
__device__ __forceinline__ void mma_f16(float* d, const uint32_t* a, const uint32_t* b) {
    asm volatile(
        "mma.sync.aligned.m16n8k16.row.col.f32.f16.f16.f32 "
        "{%0,%1,%2,%3}, {%4,%5,%6,%7}, {%8,%9}, {%0,%1,%2,%3};"
        : "+f"(d[0]), "+f"(d[1]), "+f"(d[2]), "+f"(d[3])
        : "r"(a[0]), "r"(a[1]), "r"(a[2]), "r"(a[3]), "r"(b[0]), "r"(b[1]));
}

// ---------------- x -> fp16 copy ----------------
__global__ void cvtx_kernel(const float* __restrict__ X, __half* __restrict__ Xh) {
    size_t i = ((size_t)blockIdx.x * 256 + threadIdx.x) * 4;
    float4 v = *(const float4*)(X + i);
    __half2 h0 = __floats2half2_rn(v.x, v.y);
    __half2 h1 = __floats2half2_rn(v.z, v.w);
    *(__half2*)(Xh + i)     = h0;
    *(__half2*)(Xh + i + 2) = h1;
}

// ---------------- weight transpose -> fp16 ----------------
__global__ void transcvt_kernel(const float* __restrict__ W, int ldw, int perm,
                                __half* __restrict__ T)
{
    __shared__ float t[32][33];
    const int nb = blockIdx.x * 32, kb = blockIdx.y * 32;
    const int tx = threadIdx.x & 31, ty = threadIdx.x >> 5;
    int n = nb + tx;
    int sc = perm ? (n < 1024 ? n : (n < 2048 ? n + 1024 : n - 1024)) : n;
#pragma unroll
    for (int i = 0; i < 4; i++)
        t[ty + 8 * i][tx] = W[(size_t)(kb + ty + 8 * i) * ldw + sc];
    __syncthreads();
#pragma unroll
    for (int i = 0; i < 4; i++) {
        int nn = nb + ty + 8 * i, kk = kb + tx;
        T[(size_t)nn * HID + kk] = __float2half_rn(t[tx][ty + 8 * i]);
    }
}

// ---------------- sum over H of x and img ----------------
__global__ void sumhw_kernel(const float* __restrict__ x, const float* __restrict__ img,
                             __half* __restrict__ xs, float* __restrict__ is_)
{
    int idx = blockIdx.x * 256 + threadIdx.x;
    int r = idx >> 10;
    int b = r / WW, w = r % WW;
    size_t base = ((size_t)b * (HH * WW) + w) * HID + (idx & 1023);
    float s1 = 0.f, s2 = 0.f;
#pragma unroll 4
    for (int h = 0; h < HH; h++) {
        s1 += x[base];
        s2 += img[base];
        base += (size_t)WW * HID;
    }
    xs[idx] = __float2half_rn(s1);
    is_[idx] = s2;
}

// ---------------- FP16 GEMM: C[M,N] = A[M,1024] @ Bt[N,1024]^T ----------------
// Tiles 128x128, K-chunk 64, 3-stage cp.async pipeline, 8 warps (warp tile 32x64).
#define FOFF_B 16384
#define FSTAGE 32768
#define FSMEM  (3 * FSTAGE)   // 98304

__global__ void __launch_bounds__(256, 2) gemm_f16(
    const __half* __restrict__ A, const __half* __restrict__ Bt,
    float* __restrict__ C, const float* __restrict__ Add,
    int ldc, int mode)
{
    extern __shared__ char smem[];
    const uint32_t sb = smem_u32(smem);
    const int tid = threadIdx.x, lane = tid & 31, wid = tid >> 5;
    const int warp_m = wid & 3, warp_n = wid >> 2;
    const int mBase = blockIdx.y * 128, nBase = blockIdx.x * 128;

    float acc[2][8][4];
#pragma unroll
    for (int m = 0; m < 2; m++)
#pragma unroll
        for (int n = 0; n < 8; n++)
#pragma unroll
            for (int j = 0; j < 4; j++) acc[m][n][j] = 0.f;

    // loader: A tile 128 rows x 64 halves = 16KB = 1024x16B; 4 chunks/thread; same for B
    auto load_stage = [&](int c, int s) {
        uint32_t st = sb + s * FSTAGE;
        int k0 = c * 64;
#pragma unroll
        for (int i = 0; i < 4; i++) {
            int q = tid + i * 256;
            int row = q >> 3, cc = q & 7;
            uint32_t so = SWZ(row * 128 + cc * 16);
            cp16(st + so,          A  + (size_t)(mBase + row) * HID + k0 + cc * 8);
            cp16(st + FOFF_B + so, Bt + (size_t)(nBase + row) * HID + k0 + cc * 8);
        }
        cp_commit();
    };

    load_stage(0, 0);
    load_stage(1, 1);

    const int arow = (lane & 15);
    const int chi  = (lane & 16) ? 16 : 0;

    for (int c = 0; c < 16; c++) {
        if (c == 15) cp_waitg<0>(); else cp_waitg<1>();
        __syncthreads();
        if (c + 2 < 16) load_stage(c + 2, (c + 2) % 3);

        const uint32_t st = sb + (c % 3) * FSTAGE;
#pragma unroll
        for (int ks = 0; ks < 4; ks++) {
            const int coloff = ks * 32 + chi;      // k16 = 32 bytes
            uint32_t a[2][4];
#pragma unroll
            for (int mt = 0; mt < 2; mt++) {
                int row = warp_m * 32 + mt * 16 + arow;
                ldm_x4(a[mt][0], a[mt][1], a[mt][2], a[mt][3],
                       st + SWZ(row * 128 + coloff));
            }
#pragma unroll
            for (int np = 0; np < 4; np++) {
                int rn = warp_n * 64 + np * 16 + arow;
                uint32_t r0, r1, r2, r3;
                ldm_x4(r0, r1, r2, r3, st + FOFF_B + SWZ(rn * 128 + coloff));
                uint32_t b0[2] = {r0, r2}, b1[2] = {r1, r3};
#pragma unroll
                for (int mt = 0; mt < 2; mt++) {
                    mma_f16(acc[mt][2 * np],     a[mt], b0);
                    mma_f16(acc[mt][2 * np + 1], a[mt], b1);
                }
            }
        }
    }

    // epilogue: float2 stores
#pragma unroll
    for (int mt = 0; mt < 2; mt++) {
#pragma unroll
        for (int nt = 0; nt < 8; nt++) {
            int r0 = mBase + warp_m * 32 + mt * 16 + (lane >> 2);
            int cc = nBase + warp_n * 64 + nt * 8 + 2 * (lane & 3);
#pragma unroll
            for (int half = 0; half < 2; half++) {
                int r = r0 + half * 8;
                float2 v = make_float2(acc[mt][nt][half * 2], acc[mt][nt][half * 2 + 1]);
                size_t o = (size_t)r * ldc + cc;
                if (mode == 1) {
                    float2 ad = *(const float2*)(Add + o);
                    v.x += ALPHA_F * ad.x;
                    v.y += ALPHA_F * ad.y;
                } else if (mode == 2) {
                    int ic = cc & 1023;
                    float2 ad = *(const float2*)(Add + (size_t)r * 1024 + ic);
                    v.x += ALPHA_F * ad.x;
                    v.y += ALPHA_F * ad.y;
                    if (cc >= 1024) {
                        float g = 1.f - exp2f(-(float)(5 + (ic >> 6)));
                        v.x *= g; v.y *= g;
                    }
                }
                *(float2*)(C + o) = v;
            }
        }
    }
}

// ---------------- attention per (b,n,h), register-tiled ----------------
#define RS 65
#define SS 29

__global__ void __launch_bounds__(256) attn_kernel(
    const float* __restrict__ Yqk, const float* __restrict__ vsum,
    float* __restrict__ O, float2* __restrict__ part)
{
    __shared__ float rq[28 * RS], rk[28 * RS], qs[28 * RS], ks[28 * RS], vs[28 * RS];
    __shared__ float sc[28 * SS];
    __shared__ float shred[16];

    const int id = blockIdx.x;
    const int h  = id % HH;
    const int bn = id / HH;
    const int n  = bn & (NH - 1);
    const int b  = bn >> 4;
    const int tid = threadIdx.x;

    for (int i = tid; i < 1792; i += 256) {
        int xr = i >> 6, d = i & 63;
        size_t rowbase = ((size_t)b * (HH * WW) + h * WW + xr);
        size_t gq = rowbase * 2048 + n * DH + d;
        rq[xr * RS + d] = Yqk[gq];
        rk[xr * RS + d] = Yqk[gq + 1024];
        vs[xr * RS + d] = vsum[(((size_t)b * WW + xr) * HID) + n * DH + d];
    }
    __syncthreads();

    for (int i = tid; i < 1792; i += 256) {
        int xr = i >> 6, d = i & 63;
        int j = d & 15;
        float ang = (d < 32 ? (float)h : (float)xr) * expf(-(float)j * LN1E4_16);
        float s, c;
        sincosf(ang, &s, &c);
        bool second = (d & 16) != 0;
        int pd = second ? d - 16 : d + 16;
        float sgn = second ? 1.f : -1.f;
        qs[xr * RS + d] = rq[xr * RS + d] * c + sgn * rq[xr * RS + pd] * s;
        ks[xr * RS + d] = rk[xr * RS + d] * c + sgn * rk[xr * RS + pd] * s;
    }
    __syncthreads();

    if (tid < 196) {
        int ti = tid / 14, tj = tid % 14;
        const float* q0 = qs + (2 * ti) * RS;
        const float* q1 = q0 + RS;
        const float* k0 = ks + (2 * tj) * RS;
        const float* k1 = k0 + RS;
        float a00 = 0.f, a01 = 0.f, a10 = 0.f, a11 = 0.f;
#pragma unroll 8
        for (int d = 0; d < 64; d++) {
            float qa = q0[d], qb = q1[d], ka = k0[d], kb = k1[d];
            a00 += qa * ka; a01 += qa * kb;
            a10 += qb * ka; a11 += qb * kb;
        }
        int r0 = 2 * ti, c0 = 2 * tj;
        sc[r0 * SS + c0] = a00;       sc[r0 * SS + c0 + 1] = a01;
        sc[(r0 + 1) * SS + c0] = a10; sc[(r0 + 1) * SS + c0 + 1] = a11;
    }
    __syncthreads();

    float lsum = 0.f, lss = 0.f;
    if (tid < 224) {
        int wi = tid >> 4, di = tid & 15;
        int w0 = 2 * wi, d0 = 4 * di;
        float o0[4] = {0.f, 0.f, 0.f, 0.f};
        float o1[4] = {0.f, 0.f, 0.f, 0.f};
        const float* s0p = sc + w0 * SS;
        const float* s1p = s0p + SS;
#pragma unroll 4
        for (int y = 0; y < 28; y++) {
            float s0 = s0p[y], s1 = s1p[y];
            const float* vp = vs + y * RS + d0;
#pragma unroll
            for (int j = 0; j < 4; j++) {
                float v = vp[j];
                o0[j] += s0 * v;
                o1[j] += s1 * v;
            }
        }
        size_t base = (size_t)bn * GSZ + (size_t)h * 1792;
#pragma unroll
        for (int j = 0; j < 4; j++) { lsum += o0[j] + o1[j]; lss += o0[j] * o0[j] + o1[j] * o1[j]; }
        *(float4*)(O + base + w0 * 64 + d0)       = make_float4(o0[0], o0[1], o0[2], o0[3]);
        *(float4*)(O + base + (w0 + 1) * 64 + d0) = make_float4(o1[0], o1[1], o1[2], o1[3]);
    }
#pragma unroll
    for (int o = 16; o > 0; o >>= 1) {
        lsum += __shfl_down_sync(0xffffffffu, lsum, o);
        lss  += __shfl_down_sync(0xffffffffu, lss,  o);
    }
    int w = tid >> 5, l = tid & 31;
    if (l == 0) { shred[w] = lsum; shred[8 + w] = lss; }
    __syncthreads();
    if (tid == 0) {
        float a = 0.f, b2 = 0.f;
#pragma unroll
        for (int i = 0; i < 8; i++) { a += shred[i]; b2 += shred[8 + i]; }
        part[bn * HH + h] = make_float2(a, b2);
    }
}

// ---------------- combine partials -> per-group affine ----------------
__global__ void combine_kernel(const float2* __restrict__ part,
                               const float* __restrict__ gnw, const float* __restrict__ gnb)
{
    int bn = threadIdx.x;   // 512
    float s = 0.f, ss = 0.f;
#pragma unroll
    for (int h = 0; h < HH; h++) {
        float2 p = part[bn * HH + h];
        s += p.x; ss += p.y;
    }
    float inv = 1.f / (float)GSZ;
    float mu = s * inv;
    float var = ss * inv - mu * mu;
    float rstd = rsqrtf(var + 1e-5f);
    int n = bn & (NH - 1);
    float a = rstd * gnw[n];
    g_ac[bn] = make_float2(a, gnb[n] - mu * a);
}

// ---------------- normalize + transpose -> fp16 Z ----------------
__global__ void norm_kernel(const float* __restrict__ O, __half* __restrict__ Zt)
{
    size_t i4 = ((size_t)blockIdx.x * 256 + threadIdx.x) * 4;
    int bn = (int)(i4 / GSZ);
    int rem = (int)(i4 % GSZ);
    int n = bn & (NH - 1), b = bn >> 4;
    int h = rem / (WW * DH);
    int rem2 = rem % (WW * DH);
    int w = rem2 >> 6, d = rem2 & 63;
    float2 ac = g_ac[bn];
    float4 o = *(const float4*)(O + i4);
    __half2 z0 = __floats2half2_rn(ac.x * o.x + ac.y, ac.x * o.y + ac.y);
    __half2 z1 = __floats2half2_rn(ac.x * o.z + ac.y, ac.x * o.w + ac.y);
    size_t zo = ((size_t)b * (HH * WW) + h * WW + w) * HID + n * DH + d;
    *(__half2*)(Zt + zo)     = z0;
    *(__half2*)(Zt + zo + 2) = z1;
}

// ---------------- launch ----------------
extern "C" void kernel_launch(void* const* d_in, const int* in_sizes, int n_in,
                              void* d_out, int out_size)
{
    const float* x    = (const float*)d_in[0];
    const float* img  = (const float*)d_in[1];
    const float* qkvw = (const float*)d_in[2];
    const float* ow   = (const float*)d_in[3];
    const float* gnw  = (const float*)d_in[4];
    const float* gnb  = (const float*)d_in[5];
    float* out = (float*)d_out;

    float *Yqk, *is_, *vs, *O;
    __half *xh, *xsh, *Zt, *Wt, *Ot;
    float2 *part;
    cudaGetSymbolAddress((void**)&Yqk, g_Yqk);
    cudaGetSymbolAddress((void**)&xh,  g_xh);
    cudaGetSymbolAddress((void**)&xsh, g_xsh);
    cudaGetSymbolAddress((void**)&is_, g_isum);
    cudaGetSymbolAddress((void**)&vs,  g_vsum);
    cudaGetSymbolAddress((void**)&O,   g_O);
    cudaGetSymbolAddress((void**)&Zt,  g_Zt);
    cudaGetSymbolAddress((void**)&Wt,  g_Wt);
    cudaGetSymbolAddress((void**)&Ot,  g_Ot);
    cudaGetSymbolAddress((void**)&part, g_part);

    cudaFuncSetAttribute(gemm_f16, cudaFuncAttributeMaxDynamicSharedMemorySize, FSMEM);

    // user launches 1-3
    transcvt_kernel<<<dim3(96, 32), 256>>>(qkvw, 3072, 1, Wt);
    transcvt_kernel<<<dim3(32, 32), 256>>>(ow,   1024, 0, Ot);
    cvtx_kernel<<<ROWS * HID / 1024, 256>>>(x, xh);

    // user launch 4 (ncu capture slot): Yqk = x @ [Wq|Wk] + alpha*img + gamma
    gemm_f16<<<dim3(16, 196), 256, FSMEM>>>(xh, Wt, Yqk, img, 2048, 2);

    // sums + vsum = xsum @ Wv + ALPHA*isum
    sumhw_kernel<<<3584, 256>>>(x, img, xsh, is_);
    gemm_f16<<<dim3(8, 7), 256, FSMEM>>>(xsh, Wt + (size_t)2048 * HID, vs, is_, 1024, 1);

    // attention (+ groupnorm partials)
    attn_kernel<<<BNG * HH, 256>>>(Yqk, vs, O, part);

    // groupnorm combine + normalize
    combine_kernel<<<1, 512>>>(part, gnw, gnb);
    norm_kernel<<<ROWS * HID / 1024, 256>>>(O, Zt);

    // out = Z @ o_w
    gemm_f16<<<dim3(8, 196), 256, FSMEM>>>(Zt, Ot, out, nullptr, 1024, 0);
}

// round 15
// speedup vs baseline: 6.6069x; 1.0081x over previous
#include <cuda_runtime.h>
#include <cuda_fp16.h>
#include <math.h>
#include <stdint.h>

// ---------------- problem constants ----------------
#define B_    32
#define HH    28
#define WW    28
#define HID   1024
#define NH    16
#define DH    64
#define ROWS  25088
#define BNG   512
#define GSZ   50176

#define ALPHA_F 0.0828476643f
#define LN1E4_16 0.5756462732485114f

// ---------------- scratch ----------------
__device__ float g_Yqk[(size_t)ROWS * 2048];
__device__ __half g_xh[(size_t)ROWS * HID];
__device__ __half g_xsh[B_ * WW * HID];
__device__ float g_isum[B_ * WW * HID];
__device__ float g_vsum[B_ * WW * HID];
__device__ float g_O[(size_t)BNG * GSZ];
__device__ __half g_Zt[(size_t)ROWS * HID];
__device__ __half g_Wt[(size_t)3072 * HID];
__device__ __half g_Ot[(size_t)1024 * HID];
__device__ float2 g_part[BNG * HH];
__device__ float2 g_ac[BNG];
__device__ float2 g_ropetab[28 * 16];

// ---------------- helpers ----------------
__device__ __forceinline__ uint32_t smem_u32(const void* p) {
    uint32_t a;
    asm("{ .reg .u64 t; cvta.to.shared.u64 t, %1; cvt.u32.u64 %0, t; }" : "=r"(a) : "l"(p));
    return a;
}
#define SWZ(x) ((x) ^ (((x) >> 3) & 0x70))

__device__ __forceinline__ void cp16(uint32_t saddr, const void* g) {
    asm volatile("cp.async.cg.shared.global [%0], [%1], 16;" :: "r"(saddr), "l"(g));
}
__device__ __forceinline__ void cp_commit() {
    asm volatile("cp.async.commit_group;" ::: "memory");
}
template <int N>
__device__ __forceinline__ void cp_waitg() {
    asm volatile("cp.async.wait_group %0;" :: "n"(N) : "memory");
}
__device__ __forceinline__ void ldm_x4(uint32_t& r0, uint32_t& r1, uint32_t& r2, uint32_t& r3,
                                       uint32_t addr) {
    asm volatile("ldmatrix.sync.aligned.m8n8.x4.shared.b16 {%0,%1,%2,%3}, [%4];"
                 : "=r"(r0), "=r"(r1), "=r"(r2), "=r"(r3) : "r"(addr));
}
__device__ __forceinline__ void mma_f16(float* d, const uint32_t* a, const uint32_t* b) {
    asm volatile(
        "mma.sync.aligned.m16n8k16.row.col.f32.f16.f16.f32 "
        "{%0,%1,%2,%3}, {%4,%5,%6,%7}, {%8,%9}, {%0,%1,%2,%3};"
        : "+f"(d[0]), "+f"(d[1]), "+f"(d[2]), "+f"(d[3])
        : "r"(a[0]), "r"(a[1]), "r"(a[2]), "r"(a[3]), "r"(b[0]), "r"(b[1]));
}

// ---------------- rope table: cos/sin(idx * 10000^(-j/16)) ----------------
__global__ void ropetab_kernel(float2* __restrict__ tab) {
    int i = threadIdx.x;              // 448
    int idx = i >> 4, j = i & 15;
    float ang = (float)idx * expf(-(float)j * LN1E4_16);
    float s, c;
    sincosf(ang, &s, &c);
    tab[i] = make_float2(c, s);
}

// ---------------- x -> fp16 copy ----------------
__global__ void cvtx_kernel(const float* __restrict__ X, __half* __restrict__ Xh) {
    size_t i = ((size_t)blockIdx.x * 256 + threadIdx.x) * 4;
    float4 v = *(const float4*)(X + i);
    *(__half2*)(Xh + i)     = __floats2half2_rn(v.x, v.y);
    *(__half2*)(Xh + i + 2) = __floats2half2_rn(v.z, v.w);
}

// ---------------- weight transpose -> fp16 ----------------
__global__ void transcvt_kernel(const float* __restrict__ W, int ldw, int perm,
                                __half* __restrict__ T)
{
    __shared__ float t[32][33];
    const int nb = blockIdx.x * 32, kb = blockIdx.y * 32;
    const int tx = threadIdx.x & 31, ty = threadIdx.x >> 5;
    int n = nb + tx;
    int sc = perm ? (n < 1024 ? n : (n < 2048 ? n + 1024 : n - 1024)) : n;
#pragma unroll
    for (int i = 0; i < 4; i++)
        t[ty + 8 * i][tx] = W[(size_t)(kb + ty + 8 * i) * ldw + sc];
    __syncthreads();
#pragma unroll
    for (int i = 0; i < 4; i++) {
        int nn = nb + ty + 8 * i, kk = kb + tx;
        T[(size_t)nn * HID + kk] = __float2half_rn(t[tx][ty + 8 * i]);
    }
}

// ---------------- sum over H of x and img ----------------
__global__ void sumhw_kernel(const float* __restrict__ x, const float* __restrict__ img,
                             __half* __restrict__ xs, float* __restrict__ is_)
{
    int idx = blockIdx.x * 256 + threadIdx.x;
    int r = idx >> 10;
    int b = r / WW, w = r % WW;
    size_t base = ((size_t)b * (HH * WW) + w) * HID + (idx & 1023);
    float s1 = 0.f, s2 = 0.f;
#pragma unroll 4
    for (int h = 0; h < HH; h++) {
        s1 += x[base];
        s2 += img[base];
        base += (size_t)WW * HID;
    }
    xs[idx] = __float2half_rn(s1);
    is_[idx] = s2;
}

// ---------------- FP16 GEMM: C[M,N] = A[M,1024] @ Bt[N,1024]^T ----------------
// Tiles 128x128, K-chunk 64, 3-stage cp.async pipeline, 8 warps (warp tile 32x64).
// Fragment-level software pipelining: A frags double-buffered per-ks, B per-np.
#define FOFF_B 16384
#define FSTAGE 32768
#define FSMEM  (3 * FSTAGE)   // 98304

__global__ void __launch_bounds__(256, 2) gemm_f16(
    const __half* __restrict__ A, const __half* __restrict__ Bt,
    float* __restrict__ C, const float* __restrict__ Add,
    int ldc, int mode)
{
    extern __shared__ char smem[];
    const uint32_t sb = smem_u32(smem);
    const int tid = threadIdx.x, lane = tid & 31, wid = tid >> 5;
    const int warp_m = wid & 3, warp_n = wid >> 2;
    const int mBase = blockIdx.y * 128, nBase = blockIdx.x * 128;

    float acc[2][8][4];
#pragma unroll
    for (int m = 0; m < 2; m++)
#pragma unroll
        for (int n = 0; n < 8; n++)
#pragma unroll
            for (int j = 0; j < 4; j++) acc[m][n][j] = 0.f;

    auto load_stage = [&](int c, int s) {
        uint32_t st = sb + s * FSTAGE;
        int k0 = c * 64;
#pragma unroll
        for (int i = 0; i < 4; i++) {
            int q = tid + i * 256;
            int row = q >> 3, cc = q & 7;
            uint32_t so = SWZ(row * 128 + cc * 16);
            cp16(st + so,          A  + (size_t)(mBase + row) * HID + k0 + cc * 8);
            cp16(st + FOFF_B + so, Bt + (size_t)(nBase + row) * HID + k0 + cc * 8);
        }
        cp_commit();
    };

    load_stage(0, 0);
    load_stage(1, 1);

    const int arow = (lane & 15);
    const int chi  = (lane & 16) ? 16 : 0;

    uint32_t af[2][8], bf[2][4];

    for (int c = 0; c < 16; c++) {
        if (c == 15) cp_waitg<0>(); else cp_waitg<1>();
        __syncthreads();
        if (c + 2 < 16) load_stage(c + 2, (c + 2) % 3);

        const uint32_t st = sb + (c % 3) * FSTAGE;

        // prime frags for ks=0
        {
            const int coloff = chi;
            ldm_x4(af[0][0], af[0][1], af[0][2], af[0][3],
                   st + SWZ((warp_m * 32 + arow) * 128 + coloff));
            ldm_x4(af[0][4], af[0][5], af[0][6], af[0][7],
                   st + SWZ((warp_m * 32 + 16 + arow) * 128 + coloff));
            ldm_x4(bf[0][0], bf[0][1], bf[0][2], bf[0][3],
                   st + FOFF_B + SWZ((warp_n * 64 + arow) * 128 + coloff));
        }
#pragma unroll
        for (int ks = 0; ks < 4; ks++) {
            const int coloff = ks * 32 + chi;
#pragma unroll
            for (int np = 0; np < 4; np++) {
                if (np < 3) {
                    // prefetch B(ks, np+1)
                    uint32_t* d = bf[(np + 1) & 1];
                    ldm_x4(d[0], d[1], d[2], d[3],
                           st + FOFF_B + SWZ((warp_n * 64 + (np + 1) * 16 + arow) * 128 + coloff));
                } else if (ks < 3) {
                    // prefetch A(ks+1) and B(ks+1, 0)
                    const int nco = (ks + 1) * 32 + chi;
                    uint32_t* da = af[(ks + 1) & 1];
                    ldm_x4(da[0], da[1], da[2], da[3],
                           st + SWZ((warp_m * 32 + arow) * 128 + nco));
                    ldm_x4(da[4], da[5], da[6], da[7],
                           st + SWZ((warp_m * 32 + 16 + arow) * 128 + nco));
                    uint32_t* db = bf[0];
                    ldm_x4(db[0], db[1], db[2], db[3],
                           st + FOFF_B + SWZ((warp_n * 64 + arow) * 128 + nco));
                }
                const uint32_t* a0 = af[ks & 1];
                const uint32_t* bb = bf[np & 1];
                uint32_t b0[2] = {bb[0], bb[2]}, b1[2] = {bb[1], bb[3]};
                mma_f16(acc[0][2 * np],     a0,     b0);
                mma_f16(acc[0][2 * np + 1], a0,     b1);
                mma_f16(acc[1][2 * np],     a0 + 4, b0);
                mma_f16(acc[1][2 * np + 1], a0 + 4, b1);
            }
        }
    }

    // epilogue
#pragma unroll
    for (int mt = 0; mt < 2; mt++) {
#pragma unroll
        for (int nt = 0; nt < 8; nt++) {
            int r0 = mBase + warp_m * 32 + mt * 16 + (lane >> 2);
            int cc = nBase + warp_n * 64 + nt * 8 + 2 * (lane & 3);
#pragma unroll
            for (int half = 0; half < 2; half++) {
                int r = r0 + half * 8;
                float2 v = make_float2(acc[mt][nt][half * 2], acc[mt][nt][half * 2 + 1]);
                size_t o = (size_t)r * ldc + cc;
                if (mode == 1) {
                    float2 ad = *(const float2*)(Add + o);
                    v.x += ALPHA_F * ad.x;
                    v.y += ALPHA_F * ad.y;
                } else if (mode == 2) {
                    int ic = cc & 1023;
                    float2 ad = *(const float2*)(Add + (size_t)r * 1024 + ic);
                    v.x += ALPHA_F * ad.x;
                    v.y += ALPHA_F * ad.y;
                    if (cc >= 1024) {
                        float g = 1.f - exp2f(-(float)(5 + (ic >> 6)));
                        v.x *= g; v.y *= g;
                    }
                }
                *(float2*)(C + o) = v;
            }
        }
    }
}

// ---------------- attention per (b,n,h), register-tiled, table rope ----------------
#define RS 65
#define SS 29

__global__ void __launch_bounds__(256) attn_kernel(
    const float* __restrict__ Yqk, const float* __restrict__ vsum,
    const float2* __restrict__ ropetab,
    float* __restrict__ O, float2* __restrict__ part)
{
    __shared__ float rq[28 * RS], rk[28 * RS], qs[28 * RS], ks[28 * RS], vs[28 * RS];
    __shared__ float sc[28 * SS];
    __shared__ float2 stab[448];
    __shared__ float shred[16];

    const int id = blockIdx.x;
    const int h  = id % HH;
    const int bn = id / HH;
    const int n  = bn & (NH - 1);
    const int b  = bn >> 4;
    const int tid = threadIdx.x;

    if (tid < 448) stab[tid] = ropetab[tid];
    if (tid + 256 < 448) stab[tid + 256] = ropetab[tid + 256];

    for (int i = tid; i < 1792; i += 256) {
        int xr = i >> 6, d = i & 63;
        size_t rowbase = ((size_t)b * (HH * WW) + h * WW + xr);
        size_t gq = rowbase * 2048 + n * DH + d;
        rq[xr * RS + d] = Yqk[gq];
        rk[xr * RS + d] = Yqk[gq + 1024];
        vs[xr * RS + d] = vsum[(((size_t)b * WW + xr) * HID) + n * DH + d];
    }
    __syncthreads();

    for (int i = tid; i < 1792; i += 256) {
        int xr = i >> 6, d = i & 63;
        int sel = (d < 32) ? h : xr;
        float2 cs = stab[sel * 16 + (d & 15)];
        bool second = (d & 16) != 0;
        int pd = second ? d - 16 : d + 16;
        float sgn = second ? 1.f : -1.f;
        qs[xr * RS + d] = rq[xr * RS + d] * cs.x + sgn * rq[xr * RS + pd] * cs.y;
        ks[xr * RS + d] = rk[xr * RS + d] * cs.x + sgn * rk[xr * RS + pd] * cs.y;
    }
    __syncthreads();

    if (tid < 196) {
        int ti = tid / 14, tj = tid % 14;
        const float* q0 = qs + (2 * ti) * RS;
        const float* q1 = q0 + RS;
        const float* k0 = ks + (2 * tj) * RS;
        const float* k1 = k0 + RS;
        float a00 = 0.f, a01 = 0.f, a10 = 0.f, a11 = 0.f;
#pragma unroll 8
        for (int d = 0; d < 64; d++) {
            float qa = q0[d], qb = q1[d], ka = k0[d], kb = k1[d];
            a00 += qa * ka; a01 += qa * kb;
            a10 += qb * ka; a11 += qb * kb;
        }
        int r0 = 2 * ti, c0 = 2 * tj;
        sc[r0 * SS + c0] = a00;       sc[r0 * SS + c0 + 1] = a01;
        sc[(r0 + 1) * SS + c0] = a10; sc[(r0 + 1) * SS + c0 + 1] = a11;
    }
    __syncthreads();

    float lsum = 0.f, lss = 0.f;
    if (tid < 224) {
        int wi = tid >> 4, di = tid & 15;
        int w0 = 2 * wi, d0 = 4 * di;
        float o0[4] = {0.f, 0.f, 0.f, 0.f};
        float o1[4] = {0.f, 0.f, 0.f, 0.f};
        const float* s0p = sc + w0 * SS;
        const float* s1p = s0p + SS;
#pragma unroll 4
        for (int y = 0; y < 28; y++) {
            float s0 = s0p[y], s1 = s1p[y];
            const float* vp = vs + y * RS + d0;
#pragma unroll
            for (int j = 0; j < 4; j++) {
                float v = vp[j];
                o0[j] += s0 * v;
                o1[j] += s1 * v;
            }
        }
        size_t base = (size_t)bn * GSZ + (size_t)h * 1792;
#pragma unroll
        for (int j = 0; j < 4; j++) { lsum += o0[j] + o1[j]; lss += o0[j] * o0[j] + o1[j] * o1[j]; }
        *(float4*)(O + base + w0 * 64 + d0)       = make_float4(o0[0], o0[1], o0[2], o0[3]);
        *(float4*)(O + base + (w0 + 1) * 64 + d0) = make_float4(o1[0], o1[1], o1[2], o1[3]);
    }
#pragma unroll
    for (int o = 16; o > 0; o >>= 1) {
        lsum += __shfl_down_sync(0xffffffffu, lsum, o);
        lss  += __shfl_down_sync(0xffffffffu, lss,  o);
    }
    int w = tid >> 5, l = tid & 31;
    if (l == 0) { shred[w] = lsum; shred[8 + w] = lss; }
    __syncthreads();
    if (tid == 0) {
        float a = 0.f, b2 = 0.f;
#pragma unroll
        for (int i = 0; i < 8; i++) { a += shred[i]; b2 += shred[8 + i]; }
        part[bn * HH + h] = make_float2(a, b2);
    }
}

// ---------------- combine partials -> per-group affine ----------------
__global__ void combine_kernel(const float2* __restrict__ part,
                               const float* __restrict__ gnw, const float* __restrict__ gnb)
{
    int bn = threadIdx.x;   // 512
    float s = 0.f, ss = 0.f;
#pragma unroll
    for (int h = 0; h < HH; h++) {
        float2 p = part[bn * HH + h];
        s += p.x; ss += p.y;
    }
    float inv = 1.f / (float)GSZ;
    float mu = s * inv;
    float var = ss * inv - mu * mu;
    float rstd = rsqrtf(var + 1e-5f);
    int n = bn & (NH - 1);
    float a = rstd * gnw[n];
    g_ac[bn] = make_float2(a, gnb[n] - mu * a);
}

// ---------------- normalize + transpose -> fp16 Z ----------------
__global__ void norm_kernel(const float* __restrict__ O, __half* __restrict__ Zt)
{
    size_t i4 = ((size_t)blockIdx.x * 256 + threadIdx.x) * 4;
    int bn = (int)(i4 / GSZ);
    int rem = (int)(i4 % GSZ);
    int n = bn & (NH - 1), b = bn >> 4;
    int h = rem / (WW * DH);
    int rem2 = rem % (WW * DH);
    int w = rem2 >> 6, d = rem2 & 63;
    float2 ac = g_ac[bn];
    float4 o = *(const float4*)(O + i4);
    __half2 z0 = __floats2half2_rn(ac.x * o.x + ac.y, ac.x * o.y + ac.y);
    __half2 z1 = __floats2half2_rn(ac.x * o.z + ac.y, ac.x * o.w + ac.y);
    size_t zo = ((size_t)b * (HH * WW) + h * WW + w) * HID + n * DH + d;
    *(__half2*)(Zt + zo)     = z0;
    *(__half2*)(Zt + zo + 2) = z1;
}

// ---------------- launch ----------------
extern "C" void kernel_launch(void* const* d_in, const int* in_sizes, int n_in,
                              void* d_out, int out_size)
{
    const float* x    = (const float*)d_in[0];
    const float* img  = (const float*)d_in[1];
    const float* qkvw = (const float*)d_in[2];
    const float* ow   = (const float*)d_in[3];
    const float* gnw  = (const float*)d_in[4];
    const float* gnb  = (const float*)d_in[5];
    float* out = (float*)d_out;

    float *Yqk, *is_, *vs, *O;
    __half *xh, *xsh, *Zt, *Wt, *Ot;
    float2 *part, *rtab;
    cudaGetSymbolAddress((void**)&Yqk, g_Yqk);
    cudaGetSymbolAddress((void**)&xh,  g_xh);
    cudaGetSymbolAddress((void**)&xsh, g_xsh);
    cudaGetSymbolAddress((void**)&is_, g_isum);
    cudaGetSymbolAddress((void**)&vs,  g_vsum);
    cudaGetSymbolAddress((void**)&O,   g_O);
    cudaGetSymbolAddress((void**)&Zt,  g_Zt);
    cudaGetSymbolAddress((void**)&Wt,  g_Wt);
    cudaGetSymbolAddress((void**)&Ot,  g_Ot);
    cudaGetSymbolAddress((void**)&part, g_part);
    cudaGetSymbolAddress((void**)&rtab, g_ropetab);

    cudaFuncSetAttribute(gemm_f16, cudaFuncAttributeMaxDynamicSharedMemorySize, FSMEM);

    // user launches 1-3
    transcvt_kernel<<<dim3(96, 32), 256>>>(qkvw, 3072, 1, Wt);
    transcvt_kernel<<<dim3(32, 32), 256>>>(ow,   1024, 0, Ot);
    cvtx_kernel<<<ROWS * HID / 1024, 256>>>(x, xh);

    // user launch 4 (ncu capture slot): Yqk = x @ [Wq|Wk] + alpha*img + gamma
    gemm_f16<<<dim3(16, 196), 256, FSMEM>>>(xh, Wt, Yqk, img, 2048, 2);

    // rope table + sums + vsum
    ropetab_kernel<<<1, 448>>>(rtab);
    sumhw_kernel<<<3584, 256>>>(x, img, xsh, is_);
    gemm_f16<<<dim3(8, 7), 256, FSMEM>>>(xsh, Wt + (size_t)2048 * HID, vs, is_, 1024, 1);

    // attention (+ groupnorm partials)
    attn_kernel<<<BNG * HH, 256>>>(Yqk, vs, rtab, O, part);

    // groupnorm combine + normalize
    combine_kernel<<<1, 512>>>(part, gnw, gnb);
    norm_kernel<<<ROWS * HID / 1024, 256>>>(O, Zt);

    // out = Z @ o_w
    gemm_f16<<<dim3(8, 196), 256, FSMEM>>>(Zt, Ot, out, nullptr, 1024, 0);
}